// round 12
// baseline (speedup 1.0000x reference)
#include <cuda_runtime.h>
#include <cuda_bf16.h>
#include <cstdint>
#include <math.h>

#define BB   8
#define HD   128
#define WD   128
#define CC   256
#define HW   16384
#define NPLANE 2048
#define TWOPI 6.28318530717958647692f

// ---------------- scratch ----------------
__device__ float2 g_AF[CC * HW];
__device__ float2 g_BF[CC * HW];
__device__ float2 g_XF[NPLANE * HW];
__device__ float2 g_GA[NPLANE * HW];
__device__ float2 g_GB[NPLANE * HW];
__device__ __align__(16) __nv_bfloat16 g_WbHi[1024 * 256];   // [n][k], n = d*4+m
__device__ __align__(16) __nv_bfloat16 g_WbLo[1024 * 256];
__device__ __align__(16) __nv_bfloat16 g_XHi[131072 * 256];  // [pix][c] bf16 hi
__device__ __align__(16) __nv_bfloat16 g_XLo[131072 * 256];  // [pix][c] bf16 lo
__device__ float  g_bpk[1024];

// ---------------- complex helpers ----------------
__device__ __forceinline__ float2 cmul(float2 a, float2 b) {
    return make_float2(a.x * b.x - a.y * b.y, a.x * b.y + a.y * b.x);
}
__device__ __forceinline__ float2 cadd(float2 a, float2 b) { return make_float2(a.x + b.x, a.y + b.y); }
__device__ __forceinline__ float2 csub(float2 a, float2 b) { return make_float2(a.x - b.x, a.y - b.y); }
__device__ __forceinline__ float2 cconj(float2 a) { return make_float2(a.x, -a.y); }

__device__ __forceinline__ float2 shfl_xor_c(float2 v, int m) {
    float2 r;
    r.x = __shfl_xor_sync(0xffffffffu, v.x, m);
    r.y = __shfl_xor_sync(0xffffffffu, v.y, m);
    return r;
}

__device__ __forceinline__ uint32_t smem_u32(const void* p) {
    uint32_t a;
    asm("{ .reg .u64 t; cvta.to.shared.u64 t, %1; cvt.u32.u64 %0, t; }" : "=r"(a) : "l"(p));
    return a;
}
__device__ __forceinline__ void ldsm4(uint32_t* r, uint32_t addr) {
    asm volatile("ldmatrix.sync.aligned.m8n8.x4.shared.b16 {%0,%1,%2,%3}, [%4];"
                 : "=r"(r[0]), "=r"(r[1]), "=r"(r[2]), "=r"(r[3]) : "r"(addr));
}
__device__ __forceinline__ void mma16816(float* c, const uint32_t* a, const uint32_t* b) {
    asm volatile("mma.sync.aligned.m16n8k16.row.col.f32.bf16.bf16.f32 "
                 "{%0,%1,%2,%3}, {%4,%5,%6,%7}, {%8,%9}, {%0,%1,%2,%3};"
                 : "+f"(c[0]), "+f"(c[1]), "+f"(c[2]), "+f"(c[3])
                 : "r"(a[0]), "r"(a[1]), "r"(a[2]), "r"(a[3]), "r"(b[0]), "r"(b[1]));
}
__device__ __forceinline__ void cp16(uint32_t dst, const void* src) {
    asm volatile("cp.async.cg.shared.global [%0], [%1], 16;" :: "r"(dst), "l"(src) : "memory");
}
#define CP_COMMIT() asm volatile("cp.async.commit_group;" ::: "memory")
#define CP_WAIT1()  asm volatile("cp.async.wait_group 1;" ::: "memory")
#define CP_WAIT0()  asm volatile("cp.async.wait_group 0;" ::: "memory")

// 128-pt FFT: 4 regs x 32 lanes. Natural in; out reg k1 @ lane t = index 4*brev5(t)+k1.
template <int SGN>
__device__ __forceinline__ void fft128(float2 v[4], int lane) {
    float2 t0 = cadd(v[0], v[2]);
    float2 t1 = csub(v[0], v[2]);
    float2 t2 = cadd(v[1], v[3]);
    float2 t3 = csub(v[1], v[3]);
    float2 jt3 = make_float2(-t3.y, t3.x);
    float2 y0 = cadd(t0, t2);
    float2 y2 = csub(t0, t2);
    float2 y1, y3;
    if (SGN < 0) { y1 = csub(t1, jt3); y3 = cadd(t1, jt3); }
    else         { y1 = cadd(t1, jt3); y3 = csub(t1, jt3); }
    float ss, cc;
    __sincosf((float)SGN * TWOPI * (float)lane * (1.0f / 128.0f), &ss, &cc);
    float2 w1 = make_float2(cc, ss);
    float2 w2 = cmul(w1, w1);
    float2 w3 = cmul(w2, w1);
    v[0] = y0;
    v[1] = cmul(y1, w1);
    v[2] = cmul(y2, w2);
    v[3] = cmul(y3, w3);
#pragma unroll
    for (int h = 16; h >= 1; h >>= 1) {
        int j = lane & (h - 1);
        float ang = (float)SGN * TWOPI * (float)j / (float)(2 * h);
        float ws, wc;
        __sincosf(ang, &ws, &wc);
        float2 w = make_float2(wc, ws);
        bool hi = (lane & h) != 0;
#pragma unroll
        for (int k = 0; k < 4; k++) {
            float2 o = shfl_xor_c(v[k], h);
            if (hi) v[k] = cmul(csub(o, v[k]), w);
            else    v[k] = cadd(v[k], o);
        }
    }
}

// ---------------- K0: pack weights (bf16 hi/lo, [n][k]) + biases ----------------
__global__ void pack_kernel(const float* __restrict__ Wma, const float* __restrict__ Wpa,
                            const float* __restrict__ Wmb, const float* __restrict__ Wpb,
                            const float* __restrict__ bma, const float* __restrict__ bpa,
                            const float* __restrict__ bmb, const float* __restrict__ bpb) {
    int i = blockIdx.x * 256 + threadIdx.x;
    if (i < 1024 * 256) {
        int n = i >> 8, k = i & 255;
        int d = n >> 2, m = n & 3;
        const float* Wm = (m == 0) ? Wma : (m == 1) ? Wpa : (m == 2) ? Wmb : Wpb;
        float w = Wm[k * 256 + d];
        __nv_bfloat16 hi = __float2bfloat16(w);
        __nv_bfloat16 lo = __float2bfloat16(w - __bfloat162float(hi));
        g_WbHi[(size_t)n * 256 + k] = hi;
        g_WbLo[(size_t)n * 256 + k] = lo;
    }
    if (i < 1024) {
        int d = i >> 2, m = i & 3;
        const float* bv = (m == 0) ? bma : (m == 1) ? bpa : (m == 2) ? bmb : bpb;
        g_bpk[i] = bv[d];
    }
}

// ---------------- K1: freq-domain conv kernels (49-tap DFT) ----------------
__global__ void kfreq_kernel(const float* __restrict__ Ak, const float* __restrict__ Bk) {
    int w = threadIdx.x;
    int h = blockIdx.x;
    int c = blockIdx.y;
    __shared__ float ka[49], kb[49];
    if (threadIdx.x < 49) {
        ka[threadIdx.x] = Ak[c * 49 + threadIdx.x];
        kb[threadIdx.x] = Bk[c * 49 + threadIdx.x];
    }
    __syncthreads();
    float2 eh[7], ew[7];
    {
        float s, ct;
        sincosf(-TWOPI * (float)h * (1.0f / 128.0f), &s, &ct);
        float2 b1 = make_float2(ct, s);
        eh[3] = make_float2(1.f, 0.f);
        eh[4] = b1; eh[5] = cmul(b1, b1); eh[6] = cmul(eh[5], b1);
        eh[2] = cconj(eh[4]); eh[1] = cconj(eh[5]); eh[0] = cconj(eh[6]);
        sincosf(-TWOPI * (float)w * (1.0f / 128.0f), &s, &ct);
        float2 b2 = make_float2(ct, s);
        ew[3] = make_float2(1.f, 0.f);
        ew[4] = b2; ew[5] = cmul(b2, b2); ew[6] = cmul(ew[5], b2);
        ew[2] = cconj(ew[4]); ew[1] = cconj(ew[5]); ew[0] = cconj(ew[6]);
    }
    float2 accA = make_float2(0.f, 0.f), accB = make_float2(0.f, 0.f);
#pragma unroll
    for (int i = 0; i < 7; i++) {
        float2 rowA = make_float2(0.f, 0.f), rowB = make_float2(0.f, 0.f);
#pragma unroll
        for (int j = 0; j < 7; j++) {
            float va = ka[i * 7 + j], vb = kb[i * 7 + j];
            rowA.x += va * ew[j].x; rowA.y += va * ew[j].y;
            rowB.x += vb * ew[j].x; rowB.y += vb * ew[j].y;
        }
        accA = cadd(accA, cmul(eh[i], rowA));
        accB = cadd(accB, cmul(eh[i], rowB));
    }
    size_t idx = (size_t)c * HW + h * 128 + w;
    g_AF[idx] = accA;
    g_BF[idx] = accB;
}

// ---------------- K3: FFT along W + transpose to planar + bf16 split of x ----------------
__global__ void fftw_kernel(const float* __restrict__ x) {
    __shared__ float tile[128][33];
    int bh = blockIdx.y;
    int b = bh >> 7;
    int c0 = blockIdx.x * 32;
    int t = threadIdx.x;
#pragma unroll
    for (int j = 0; j < 16; j++) {
        int i = t + j * 256;
        int w = i >> 5, cl = i & 31;
        float v = x[(size_t)bh * (WD * CC) + (size_t)w * CC + c0 + cl];
        tile[w][cl] = v;
        __nv_bfloat16 hi = __float2bfloat16(v);
        __nv_bfloat16 lo = __float2bfloat16(v - __bfloat162float(hi));
        size_t pi = ((size_t)bh * 128 + w) * 256 + c0 + cl;
        g_XHi[pi] = hi;
        g_XLo[pi] = lo;
    }
    __syncthreads();
    int warp = t >> 5, lane = t & 31;
    int rb = __brev(lane) >> 27;
    int h = bh & 127;
#pragma unroll
    for (int cc4 = 0; cc4 < 4; cc4++) {
        int cl = warp * 4 + cc4;
        float2 v[4];
#pragma unroll
        for (int n1 = 0; n1 < 4; n1++) v[n1] = make_float2(tile[n1 * 32 + lane][cl], 0.f);
        fft128<-1>(v, lane);
        size_t rowoff = (size_t)(b * CC + c0 + cl) * HW + (size_t)h * 128 + rb * 4;
#pragma unroll
        for (int k1 = 0; k1 < 4; k1++) g_XF[rowoff + k1] = v[k1];
    }
}

// ---------------- K2: HMMA GEMM, cp.async 2-stage pipeline, 2 CTAs/SM ----------------
// CTA: 128 pixels x 128 effcols; 8 warps (4 m x 2 n), warp tile 32x64.
// K=256 in 8 chunks of 32; stage = {Ah,Al,Bh,Bl}[128][40] bf16 = 40 KB; 2 stages = 80 KB.
#define AS_STRIDE_B 80                        // 40 elems * 2B
#define OFF_AH 0
#define OFF_AL 10240
#define OFF_BH 20480
#define OFF_BL 30720
#define STAGE_BYTES 40960
#define GEMM_SMEM (2 * STAGE_BYTES)           // 81920; Z tile (128*130*4=66560) aliases
#define Z_STRIDE 130

__device__ __forceinline__ void gemm_issue_stage(uint32_t sb, size_t pixbase, int n0,
                                                 int kc, int tid) {
    uint32_t st = sb + (uint32_t)(kc & 1) * STAGE_BYTES;
#pragma unroll
    for (int it = 0; it < 2; it++) {
        int u = tid + it * 256;               // 0..511: row=u>>2, seg=u&3
        int row = u >> 2, seg = u & 3;
        size_t gofs = (pixbase + row) * 256 + kc * 32 + seg * 8;
        uint32_t d = (uint32_t)(row * AS_STRIDE_B + seg * 16);
        cp16(st + OFF_AH + d, g_XHi + gofs);
        cp16(st + OFF_AL + d, g_XLo + gofs);
    }
#pragma unroll
    for (int it = 0; it < 2; it++) {
        int u = tid + it * 256;
        int row = u >> 2, seg = u & 3;
        size_t gofs = (size_t)(n0 + row) * 256 + kc * 32 + seg * 8;
        uint32_t d = (uint32_t)(row * AS_STRIDE_B + seg * 16);
        cp16(st + OFF_BH + d, g_WbHi + gofs);
        cp16(st + OFF_BL + d, g_WbLo + gofs);
    }
    CP_COMMIT();
}

__global__ __launch_bounds__(256, 2) void gemm_mma_kernel() {
    extern __shared__ char smem[];
    uint32_t sb = smem_u32(smem);
    int tid = threadIdx.x;
    int lane = tid & 31, warp = tid >> 5;
    int wm = warp >> 1, wn = warp & 1;
    int n0 = blockIdx.x * 128;
    int mb = blockIdx.y;
    size_t pixbase = (size_t)mb * 128;

    float acc[2][8][4];
#pragma unroll
    for (int i = 0; i < 2; i++)
#pragma unroll
        for (int j = 0; j < 8; j++)
#pragma unroll
            for (int k = 0; k < 4; k++) acc[i][j][k] = 0.f;

    int sub = lane >> 3, l7 = lane & 7;
    int a_r = ((sub & 1) << 3) + l7;
    int a_k = (sub >> 1) << 3;
    int b_r = ((sub >> 1) << 3) + l7;
    int b_k = (sub & 1) << 3;

    gemm_issue_stage(sb, pixbase, n0, 0, tid);
    gemm_issue_stage(sb, pixbase, n0, 1, tid);

#pragma unroll 1
    for (int kc = 0; kc < 8; kc++) {
        if (kc < 7) { CP_WAIT1(); } else { CP_WAIT0(); }
        __syncthreads();
        uint32_t st = sb + (uint32_t)(kc & 1) * STAGE_BYTES;
#pragma unroll
        for (int ks = 0; ks < 2; ks++) {
            uint32_t ah[2][4], al[2][4];
#pragma unroll
            for (int mt = 0; mt < 2; mt++) {
                uint32_t aoff = (uint32_t)((wm * 32 + mt * 16 + a_r) * AS_STRIDE_B + (ks * 16 + a_k) * 2);
                ldsm4(ah[mt], st + OFF_AH + aoff);
                ldsm4(al[mt], st + OFF_AL + aoff);
            }
#pragma unroll
            for (int ntp = 0; ntp < 4; ntp++) {
                uint32_t bh[4], bl[4];
                uint32_t boff = (uint32_t)((wn * 64 + ntp * 16 + b_r) * AS_STRIDE_B + (ks * 16 + b_k) * 2);
                ldsm4(bh, st + OFF_BH + boff);
                ldsm4(bl, st + OFF_BL + boff);
#pragma unroll
                for (int mt = 0; mt < 2; mt++) {
                    mma16816(acc[mt][2 * ntp],     ah[mt], bh);
                    mma16816(acc[mt][2 * ntp + 1], ah[mt], bh + 2);
                    mma16816(acc[mt][2 * ntp],     ah[mt], bl);
                    mma16816(acc[mt][2 * ntp + 1], ah[mt], bl + 2);
                    mma16816(acc[mt][2 * ntp],     al[mt], bh);
                    mma16816(acc[mt][2 * ntp + 1], al[mt], bh + 2);
                }
            }
        }
        __syncthreads();
        if (kc + 2 < 8) gemm_issue_stage(sb, pixbase, n0, kc + 2, tid);
    }

    // ---- epilogue: Z (transposed) in SMEM, then gates ----
    float* zs = (float*)smem;
    {
        int r0 = wm * 32 + (lane >> 2);
        int c0 = wn * 64 + 2 * (lane & 3);
#pragma unroll
        for (int mt = 0; mt < 2; mt++)
#pragma unroll
            for (int nt = 0; nt < 8; nt++) {
                int rr = r0 + mt * 16;
                int cc = c0 + nt * 8;
                zs[cc * Z_STRIDE + rr]           = acc[mt][nt][0];
                zs[(cc + 1) * Z_STRIDE + rr]     = acc[mt][nt][1];
                zs[cc * Z_STRIDE + rr + 8]       = acc[mt][nt][2];
                zs[(cc + 1) * Z_STRIDE + rr + 8] = acc[mt][nt][3];
            }
    }
    __syncthreads();
    {
        int pr = tid & 127;
        int half = tid >> 7;
        int pix = mb * 128 + pr;
        int b = pix >> 14;
        int hw = pix & 16383;
#pragma unroll 1
        for (int it = 0; it < 16; it++) {
            int dl = 2 * it + half;
            int e0 = dl * 4;
            float zma = zs[e0 * Z_STRIDE + pr]       + g_bpk[n0 + e0];
            float zpa = zs[(e0 + 1) * Z_STRIDE + pr] + g_bpk[n0 + e0 + 1];
            float zmb = zs[(e0 + 2) * Z_STRIDE + pr] + g_bpk[n0 + e0 + 2];
            float zpb = zs[(e0 + 3) * Z_STRIDE + pr] + g_bpk[n0 + e0 + 3];
            float ma  = 1.0f / (1.0f + __expf(-zma));
            float mbg = 1.0f / (1.0f + __expf(-zmb));
            float sa, ca, sbp, cb;
            __sincosf(zpa, &sa, &ca);
            __sincosf(zpb, &sbp, &cb);
            int d = (n0 >> 2) + dl;
            size_t po = (size_t)(b * 256 + d) * HW + hw;
            g_GA[po] = make_float2(ma * ca, ma * sa);
            g_GB[po] = make_float2(mbg * cb, mbg * sbp);
        }
    }
}

// ---------------- K4: FFT-H + pointwise recurrence + IFFT-H ----------------
__global__ void ffth_pointwise_kernel() {
    __shared__ float2 tile[128][33];
    int plane = blockIdx.y;
    int c = plane & 255;
    int w0 = blockIdx.x * 32;
    int t = threadIdx.x;
    size_t pbase = (size_t)plane * HW;
    size_t cbase = (size_t)c * HW;
#pragma unroll
    for (int j = 0; j < 16; j++) {
        int i = t + j * 256;
        int h = i >> 5, wl = i & 31;
        tile[h][wl] = g_XF[pbase + (size_t)h * 128 + w0 + wl];
    }
    __syncthreads();
    int warp = t >> 5, lane = t & 31;
    int rb = __brev(lane) >> 27;
#pragma unroll
    for (int cc4 = 0; cc4 < 4; cc4++) {
        int wl = warp * 4 + cc4;
        float2 v[4];
#pragma unroll
        for (int n1 = 0; n1 < 4; n1++) v[n1] = tile[n1 * 32 + lane][wl];
        fft128<-1>(v, lane);
#pragma unroll
        for (int k1 = 0; k1 < 4; k1++) tile[rb * 4 + k1][wl] = v[k1];
    }
    __syncthreads();
#pragma unroll
    for (int j = 0; j < 16; j++) {
        int i = t + j * 256;
        int h = i >> 5, wl = i & 31;
        size_t off = (size_t)h * 128 + w0 + wl;
        float2 xf = tile[h][wl];
        float2 ga = g_GA[pbase + off];
        float2 gb = g_GB[pbase + off];
        float2 af = g_AF[cbase + off];
        float2 bf = g_BF[cbase + off];
        float2 a  = cmul(ga, af);
        float2 bb = cmul(cmul(gb, bf), xf);
        float2 a2 = cmul(a, a);
        float2 a4 = cmul(a2, a2);
        float2 p1 = make_float2(1.f + a.x,  a.y);
        float2 p2 = make_float2(1.f + a2.x, a2.y);
        float2 p4 = make_float2(1.f + a4.x, a4.y);
        float2 hf = cmul(bb, cmul(cmul(p1, p2), p4));
        tile[h][wl] = hf;
    }
    __syncthreads();
#pragma unroll
    for (int cc4 = 0; cc4 < 4; cc4++) {
        int wl = warp * 4 + cc4;
        float2 v[4];
#pragma unroll
        for (int n1 = 0; n1 < 4; n1++) v[n1] = tile[n1 * 32 + lane][wl];
        fft128<+1>(v, lane);
#pragma unroll
        for (int k1 = 0; k1 < 4; k1++) tile[rb * 4 + k1][wl] = v[k1];
    }
    __syncthreads();
#pragma unroll
    for (int j = 0; j < 16; j++) {
        int i = t + j * 256;
        int h = i >> 5, wl = i & 31;
        g_XF[pbase + (size_t)h * 128 + w0 + wl] = tile[h][wl];
    }
}

// ---------------- K5: IFFT along W + transpose to (B,H,W,C) real out ----------------
__global__ void ifftw_out_kernel(float* __restrict__ out) {
    __shared__ float tile[128][33];
    int bh = blockIdx.y;
    int b = bh >> 7;
    int h = bh & 127;
    int c0 = blockIdx.x * 32;
    int t = threadIdx.x;
    int warp = t >> 5, lane = t & 31;
    int rb = __brev(lane) >> 27;
    const float inv = 1.0f / 16384.0f;
#pragma unroll
    for (int cc4 = 0; cc4 < 4; cc4++) {
        int cl = warp * 4 + cc4;
        size_t rowoff = (size_t)(b * CC + c0 + cl) * HW + (size_t)h * 128;
        float2 v[4];
#pragma unroll
        for (int n1 = 0; n1 < 4; n1++) v[n1] = g_XF[rowoff + n1 * 32 + lane];
        fft128<+1>(v, lane);
#pragma unroll
        for (int k1 = 0; k1 < 4; k1++) tile[rb * 4 + k1][cl] = v[k1].x * inv;
    }
    __syncthreads();
#pragma unroll
    for (int j = 0; j < 16; j++) {
        int i = t + j * 256;
        int w = i >> 5, cl = i & 31;
        out[(size_t)bh * (WD * CC) + (size_t)w * CC + c0 + cl] = tile[w][cl];
    }
}

extern "C" void kernel_launch(void* const* d_in, const int* in_sizes, int n_in,
                              void* d_out, int out_size) {
    const float* x   = (const float*)d_in[0];
    const float* Ak  = (const float*)d_in[1];
    const float* Bk  = (const float*)d_in[2];
    const float* Wma = (const float*)d_in[3];
    const float* bma = (const float*)d_in[4];
    const float* Wpa = (const float*)d_in[5];
    const float* bpa = (const float*)d_in[6];
    const float* Wmb = (const float*)d_in[7];
    const float* bmb = (const float*)d_in[8];
    const float* Wpb = (const float*)d_in[9];
    const float* bpb = (const float*)d_in[10];
    float* out = (float*)d_out;

    cudaFuncSetAttribute(gemm_mma_kernel, cudaFuncAttributeMaxDynamicSharedMemorySize, GEMM_SMEM);

    pack_kernel<<<1024, 256>>>(Wma, Wpa, Wmb, Wpb, bma, bpa, bmb, bpb);
    kfreq_kernel<<<dim3(128, 256), 128>>>(Ak, Bk);
    fftw_kernel<<<dim3(8, 1024), 256>>>(x);
    gemm_mma_kernel<<<dim3(8, 1024), 256, GEMM_SMEM>>>();
    ffth_pointwise_kernel<<<dim3(4, 2048), 256>>>();
    ifftw_out_kernel<<<dim3(8, 1024), 256>>>(out);
}

// round 13
// speedup vs baseline: 1.5299x; 1.5299x over previous
#include <cuda_runtime.h>
#include <cuda_bf16.h>
#include <cstdint>
#include <math.h>

#define BB   8
#define HD   128
#define WD   128
#define CC   256
#define HW   16384
#define NPLANE 2048
#define TWOPI 6.28318530717958647692f

// ---------------- scratch ----------------
__device__ float2 g_AF[CC * HW];
__device__ float2 g_BF[CC * HW];
__device__ float2 g_XF[NPLANE * HW];
__device__ float2 g_GA[NPLANE * HW];
__device__ float2 g_GB[NPLANE * HW];
__device__ __align__(16) __nv_bfloat16 g_WbHi[1024 * 256];   // [n][k], n = d*4+m
__device__ __align__(16) __nv_bfloat16 g_WbLo[1024 * 256];
__device__ __align__(16) __nv_bfloat16 g_XHi[131072 * 256];  // [pix][c] bf16 hi
__device__ __align__(16) __nv_bfloat16 g_XLo[131072 * 256];  // [pix][c] bf16 lo
__device__ float  g_bpk[1024];

// ---------------- complex helpers ----------------
__device__ __forceinline__ float2 cmul(float2 a, float2 b) {
    return make_float2(a.x * b.x - a.y * b.y, a.x * b.y + a.y * b.x);
}
__device__ __forceinline__ float2 cadd(float2 a, float2 b) { return make_float2(a.x + b.x, a.y + b.y); }
__device__ __forceinline__ float2 csub(float2 a, float2 b) { return make_float2(a.x - b.x, a.y - b.y); }
__device__ __forceinline__ float2 cconj(float2 a) { return make_float2(a.x, -a.y); }

__device__ __forceinline__ float2 shfl_xor_c(float2 v, int m) {
    float2 r;
    r.x = __shfl_xor_sync(0xffffffffu, v.x, m);
    r.y = __shfl_xor_sync(0xffffffffu, v.y, m);
    return r;
}

__device__ __forceinline__ uint32_t smem_u32(const void* p) {
    uint32_t a;
    asm("{ .reg .u64 t; cvta.to.shared.u64 t, %1; cvt.u32.u64 %0, t; }" : "=r"(a) : "l"(p));
    return a;
}
__device__ __forceinline__ void ldsm4(uint32_t* r, uint32_t addr) {
    asm volatile("ldmatrix.sync.aligned.m8n8.x4.shared.b16 {%0,%1,%2,%3}, [%4];"
                 : "=r"(r[0]), "=r"(r[1]), "=r"(r[2]), "=r"(r[3]) : "r"(addr));
}
__device__ __forceinline__ void mma16816(float* c, const uint32_t* a, const uint32_t* b) {
    asm volatile("mma.sync.aligned.m16n8k16.row.col.f32.bf16.bf16.f32 "
                 "{%0,%1,%2,%3}, {%4,%5,%6,%7}, {%8,%9}, {%0,%1,%2,%3};"
                 : "+f"(c[0]), "+f"(c[1]), "+f"(c[2]), "+f"(c[3])
                 : "r"(a[0]), "r"(a[1]), "r"(a[2]), "r"(a[3]), "r"(b[0]), "r"(b[1]));
}
__device__ __forceinline__ void cp16(uint32_t dst, const void* src) {
    asm volatile("cp.async.cg.shared.global [%0], [%1], 16;" :: "r"(dst), "l"(src) : "memory");
}
#define CP_COMMIT() asm volatile("cp.async.commit_group;" ::: "memory")
#define CP_WAIT0()  asm volatile("cp.async.wait_group 0;" ::: "memory")

// 128-pt FFT: 4 regs x 32 lanes. Natural in; out reg k1 @ lane t = index 4*brev5(t)+k1.
template <int SGN>
__device__ __forceinline__ void fft128(float2 v[4], int lane) {
    float2 t0 = cadd(v[0], v[2]);
    float2 t1 = csub(v[0], v[2]);
    float2 t2 = cadd(v[1], v[3]);
    float2 t3 = csub(v[1], v[3]);
    float2 jt3 = make_float2(-t3.y, t3.x);
    float2 y0 = cadd(t0, t2);
    float2 y2 = csub(t0, t2);
    float2 y1, y3;
    if (SGN < 0) { y1 = csub(t1, jt3); y3 = cadd(t1, jt3); }
    else         { y1 = cadd(t1, jt3); y3 = csub(t1, jt3); }
    float ss, cc;
    __sincosf((float)SGN * TWOPI * (float)lane * (1.0f / 128.0f), &ss, &cc);
    float2 w1 = make_float2(cc, ss);
    float2 w2 = cmul(w1, w1);
    float2 w3 = cmul(w2, w1);
    v[0] = y0;
    v[1] = cmul(y1, w1);
    v[2] = cmul(y2, w2);
    v[3] = cmul(y3, w3);
#pragma unroll
    for (int h = 16; h >= 1; h >>= 1) {
        int j = lane & (h - 1);
        float ang = (float)SGN * TWOPI * (float)j / (float)(2 * h);
        float ws, wc;
        __sincosf(ang, &ws, &wc);
        float2 w = make_float2(wc, ws);
        bool hi = (lane & h) != 0;
#pragma unroll
        for (int k = 0; k < 4; k++) {
            float2 o = shfl_xor_c(v[k], h);
            if (hi) v[k] = cmul(csub(o, v[k]), w);
            else    v[k] = cadd(v[k], o);
        }
    }
}

// ---------------- K0: pack weights (bf16 hi/lo, [n][k]) + biases ----------------
__global__ void pack_kernel(const float* __restrict__ Wma, const float* __restrict__ Wpa,
                            const float* __restrict__ Wmb, const float* __restrict__ Wpb,
                            const float* __restrict__ bma, const float* __restrict__ bpa,
                            const float* __restrict__ bmb, const float* __restrict__ bpb) {
    int i = blockIdx.x * 256 + threadIdx.x;
    if (i < 1024 * 256) {
        int n = i >> 8, k = i & 255;
        int d = n >> 2, m = n & 3;
        const float* Wm = (m == 0) ? Wma : (m == 1) ? Wpa : (m == 2) ? Wmb : Wpb;
        float w = Wm[k * 256 + d];
        __nv_bfloat16 hi = __float2bfloat16(w);
        __nv_bfloat16 lo = __float2bfloat16(w - __bfloat162float(hi));
        g_WbHi[(size_t)n * 256 + k] = hi;
        g_WbLo[(size_t)n * 256 + k] = lo;
    }
    if (i < 1024) {
        int d = i >> 2, m = i & 3;
        const float* bv = (m == 0) ? bma : (m == 1) ? bpa : (m == 2) ? bmb : bpb;
        g_bpk[i] = bv[d];
    }
}

// ---------------- K1: freq-domain conv kernels (49-tap DFT) ----------------
__global__ void kfreq_kernel(const float* __restrict__ Ak, const float* __restrict__ Bk) {
    int w = threadIdx.x;
    int h = blockIdx.x;
    int c = blockIdx.y;
    __shared__ float ka[49], kb[49];
    if (threadIdx.x < 49) {
        ka[threadIdx.x] = Ak[c * 49 + threadIdx.x];
        kb[threadIdx.x] = Bk[c * 49 + threadIdx.x];
    }
    __syncthreads();
    float2 eh[7], ew[7];
    {
        float s, ct;
        sincosf(-TWOPI * (float)h * (1.0f / 128.0f), &s, &ct);
        float2 b1 = make_float2(ct, s);
        eh[3] = make_float2(1.f, 0.f);
        eh[4] = b1; eh[5] = cmul(b1, b1); eh[6] = cmul(eh[5], b1);
        eh[2] = cconj(eh[4]); eh[1] = cconj(eh[5]); eh[0] = cconj(eh[6]);
        sincosf(-TWOPI * (float)w * (1.0f / 128.0f), &s, &ct);
        float2 b2 = make_float2(ct, s);
        ew[3] = make_float2(1.f, 0.f);
        ew[4] = b2; ew[5] = cmul(b2, b2); ew[6] = cmul(ew[5], b2);
        ew[2] = cconj(ew[4]); ew[1] = cconj(ew[5]); ew[0] = cconj(ew[6]);
    }
    float2 accA = make_float2(0.f, 0.f), accB = make_float2(0.f, 0.f);
#pragma unroll
    for (int i = 0; i < 7; i++) {
        float2 rowA = make_float2(0.f, 0.f), rowB = make_float2(0.f, 0.f);
#pragma unroll
        for (int j = 0; j < 7; j++) {
            float va = ka[i * 7 + j], vb = kb[i * 7 + j];
            rowA.x += va * ew[j].x; rowA.y += va * ew[j].y;
            rowB.x += vb * ew[j].x; rowB.y += vb * ew[j].y;
        }
        accA = cadd(accA, cmul(eh[i], rowA));
        accB = cadd(accB, cmul(eh[i], rowB));
    }
    size_t idx = (size_t)c * HW + h * 128 + w;
    g_AF[idx] = accA;
    g_BF[idx] = accB;
}

// ---------------- K3: FFT along W + transpose to planar + bf16 split of x ----------------
__global__ void fftw_kernel(const float* __restrict__ x) {
    __shared__ float tile[128][33];
    int bh = blockIdx.y;
    int b = bh >> 7;
    int c0 = blockIdx.x * 32;
    int t = threadIdx.x;
#pragma unroll
    for (int j = 0; j < 16; j++) {
        int i = t + j * 256;
        int w = i >> 5, cl = i & 31;
        float v = x[(size_t)bh * (WD * CC) + (size_t)w * CC + c0 + cl];
        tile[w][cl] = v;
        __nv_bfloat16 hi = __float2bfloat16(v);
        __nv_bfloat16 lo = __float2bfloat16(v - __bfloat162float(hi));
        size_t pi = ((size_t)bh * 128 + w) * 256 + c0 + cl;
        g_XHi[pi] = hi;
        g_XLo[pi] = lo;
    }
    __syncthreads();
    int warp = t >> 5, lane = t & 31;
    int rb = __brev(lane) >> 27;
    int h = bh & 127;
#pragma unroll
    for (int cc4 = 0; cc4 < 4; cc4++) {
        int cl = warp * 4 + cc4;
        float2 v[4];
#pragma unroll
        for (int n1 = 0; n1 < 4; n1++) v[n1] = make_float2(tile[n1 * 32 + lane][cl], 0.f);
        fft128<-1>(v, lane);
        size_t rowoff = (size_t)(b * CC + c0 + cl) * HW + (size_t)h * 128 + rb * 4;
#pragma unroll
        for (int k1 = 0; k1 < 4; k1++) g_XF[rowoff + k1] = v[k1];
    }
}

// ---------------- K2: HMMA GEMM, 64x256 tile, serial cp.async chunks, 2 CTAs/SM ----------------
// CTA: 64 pixels x 256 effcols; 8 warps (2 m x 4 n), warp tile 32x64.
// K=256 in 4 chunks of 64; buffer = A(64x72)*2 + B(256x72)*2 bf16 = 90 KB, single stage.
#define STRD 144                              // 72 elems * 2B row stride
#define OFF_AH 0
#define OFF_AL 9216
#define OFF_BH 18432
#define OFF_BL 55296
#define GEMM_SMEM 92160                       // 90 KB; Z tile (256*66*4=67584) aliases
#define Z_STRIDE 66

__global__ __launch_bounds__(256, 2) void gemm_mma_kernel() {
    extern __shared__ char smem[];
    uint32_t sb = smem_u32(smem);
    int tid = threadIdx.x;
    int lane = tid & 31, warp = tid >> 5;
    int wm = warp >> 2, wn = warp & 3;
    int n0 = blockIdx.x * 256;
    size_t pixbase = (size_t)blockIdx.y * 64;

    float acc[2][8][4];
#pragma unroll
    for (int i = 0; i < 2; i++)
#pragma unroll
        for (int j = 0; j < 8; j++)
#pragma unroll
            for (int k = 0; k < 4; k++) acc[i][j][k] = 0.f;

    int sub = lane >> 3, l7 = lane & 7;
    int a_r = ((sub & 1) << 3) + l7;
    int a_k = (sub >> 1) << 3;
    int b_r = ((sub >> 1) << 3) + l7;
    int b_k = (sub & 1) << 3;

#pragma unroll
    for (int kc = 0; kc < 4; kc++) {
        __syncthreads();                      // buffer reuse guard
        // A: 64 rows x 64 k (hi+lo): 512 cp16 per array -> 2/thread each
        {
            int u = tid << 1;                 // 2 consecutive 16B segs per thread
            int row = u >> 3, seg = u & 7;
            size_t gofs = (pixbase + row) * 256 + kc * 64 + seg * 8;
            uint32_t d = (uint32_t)(row * STRD + seg * 16);
            cp16(sb + OFF_AH + d,      g_XHi + gofs);
            cp16(sb + OFF_AH + d + 16, g_XHi + gofs + 8);
            cp16(sb + OFF_AL + d,      g_XLo + gofs);
            cp16(sb + OFF_AL + d + 16, g_XLo + gofs + 8);
        }
        // B: 256 rows x 64 k (hi+lo): 2048 cp16 per array -> 8/thread each
#pragma unroll
        for (int it = 0; it < 8; it++) {
            int u = tid + it * 256;
            int row = u >> 3, seg = u & 7;
            size_t gofs = (size_t)(n0 + row) * 256 + kc * 64 + seg * 8;
            uint32_t d = (uint32_t)(row * STRD + seg * 16);
            cp16(sb + OFF_BH + d, g_WbHi + gofs);
            cp16(sb + OFF_BL + d, g_WbLo + gofs);
        }
        CP_COMMIT();
        CP_WAIT0();
        __syncthreads();

#pragma unroll
        for (int ks = 0; ks < 4; ks++) {
            uint32_t ah[2][4], al[2][4];
#pragma unroll
            for (int mt = 0; mt < 2; mt++) {
                uint32_t aoff = (uint32_t)((wm * 32 + mt * 16 + a_r) * STRD + (ks * 16 + a_k) * 2);
                ldsm4(ah[mt], sb + OFF_AH + aoff);
                ldsm4(al[mt], sb + OFF_AL + aoff);
            }
#pragma unroll
            for (int ntp = 0; ntp < 4; ntp++) {
                uint32_t bh[4], bl[4];
                uint32_t boff = (uint32_t)((wn * 64 + ntp * 16 + b_r) * STRD + (ks * 16 + b_k) * 2);
                ldsm4(bh, sb + OFF_BH + boff);
                ldsm4(bl, sb + OFF_BL + boff);
#pragma unroll
                for (int mt = 0; mt < 2; mt++) {
                    mma16816(acc[mt][2 * ntp],     ah[mt], bh);
                    mma16816(acc[mt][2 * ntp + 1], ah[mt], bh + 2);
                    mma16816(acc[mt][2 * ntp],     ah[mt], bl);
                    mma16816(acc[mt][2 * ntp + 1], ah[mt], bl + 2);
                    mma16816(acc[mt][2 * ntp],     al[mt], bh);
                    mma16816(acc[mt][2 * ntp + 1], al[mt], bh + 2);
                }
            }
        }
    }

    // ---- epilogue: Z (transposed, 256 cols x 64 rows) in SMEM, then gates ----
    __syncthreads();
    float* zs = (float*)smem;
    {
        int r0 = wm * 32 + (lane >> 2);
        int c0 = wn * 64 + 2 * (lane & 3);
#pragma unroll
        for (int mt = 0; mt < 2; mt++)
#pragma unroll
            for (int nt = 0; nt < 8; nt++) {
                int rr = r0 + mt * 16;
                int cc = c0 + nt * 8;
                zs[cc * Z_STRIDE + rr]           = acc[mt][nt][0];
                zs[(cc + 1) * Z_STRIDE + rr]     = acc[mt][nt][1];
                zs[cc * Z_STRIDE + rr + 8]       = acc[mt][nt][2];
                zs[(cc + 1) * Z_STRIDE + rr + 8] = acc[mt][nt][3];
            }
    }
    __syncthreads();
    {
        int pr = tid & 63;
        int dgrp = tid >> 6;                  // 0..3
        int pix = (int)pixbase + pr;
        int b = pix >> 14;
        int hw = pix & 16383;
#pragma unroll 1
        for (int it = 0; it < 16; it++) {
            int dl = dgrp + it * 4;           // 0..63
            int e0 = dl * 4;
            float zma = zs[e0 * Z_STRIDE + pr]       + g_bpk[n0 + e0];
            float zpa = zs[(e0 + 1) * Z_STRIDE + pr] + g_bpk[n0 + e0 + 1];
            float zmb = zs[(e0 + 2) * Z_STRIDE + pr] + g_bpk[n0 + e0 + 2];
            float zpb = zs[(e0 + 3) * Z_STRIDE + pr] + g_bpk[n0 + e0 + 3];
            float ma  = 1.0f / (1.0f + __expf(-zma));
            float mbg = 1.0f / (1.0f + __expf(-zmb));
            float sa, ca, sbp, cb;
            __sincosf(zpa, &sa, &ca);
            __sincosf(zpb, &sbp, &cb);
            int d = (n0 >> 2) + dl;
            size_t po = (size_t)(b * 256 + d) * HW + hw;
            g_GA[po] = make_float2(ma * ca, ma * sa);
            g_GB[po] = make_float2(mbg * cb, mbg * sbp);
        }
    }
}

// ---------------- K4: FFT-H + pointwise recurrence + IFFT-H ----------------
__global__ void ffth_pointwise_kernel() {
    __shared__ float2 tile[128][33];
    int plane = blockIdx.y;
    int c = plane & 255;
    int w0 = blockIdx.x * 32;
    int t = threadIdx.x;
    size_t pbase = (size_t)plane * HW;
    size_t cbase = (size_t)c * HW;
#pragma unroll
    for (int j = 0; j < 16; j++) {
        int i = t + j * 256;
        int h = i >> 5, wl = i & 31;
        tile[h][wl] = g_XF[pbase + (size_t)h * 128 + w0 + wl];
    }
    __syncthreads();
    int warp = t >> 5, lane = t & 31;
    int rb = __brev(lane) >> 27;
#pragma unroll
    for (int cc4 = 0; cc4 < 4; cc4++) {
        int wl = warp * 4 + cc4;
        float2 v[4];
#pragma unroll
        for (int n1 = 0; n1 < 4; n1++) v[n1] = tile[n1 * 32 + lane][wl];
        fft128<-1>(v, lane);
#pragma unroll
        for (int k1 = 0; k1 < 4; k1++) tile[rb * 4 + k1][wl] = v[k1];
    }
    __syncthreads();
#pragma unroll
    for (int j = 0; j < 16; j++) {
        int i = t + j * 256;
        int h = i >> 5, wl = i & 31;
        size_t off = (size_t)h * 128 + w0 + wl;
        float2 xf = tile[h][wl];
        float2 ga = g_GA[pbase + off];
        float2 gb = g_GB[pbase + off];
        float2 af = g_AF[cbase + off];
        float2 bf = g_BF[cbase + off];
        float2 a  = cmul(ga, af);
        float2 bb = cmul(cmul(gb, bf), xf);
        float2 a2 = cmul(a, a);
        float2 a4 = cmul(a2, a2);
        float2 p1 = make_float2(1.f + a.x,  a.y);
        float2 p2 = make_float2(1.f + a2.x, a2.y);
        float2 p4 = make_float2(1.f + a4.x, a4.y);
        float2 hf = cmul(bb, cmul(cmul(p1, p2), p4));
        tile[h][wl] = hf;
    }
    __syncthreads();
#pragma unroll
    for (int cc4 = 0; cc4 < 4; cc4++) {
        int wl = warp * 4 + cc4;
        float2 v[4];
#pragma unroll
        for (int n1 = 0; n1 < 4; n1++) v[n1] = tile[n1 * 32 + lane][wl];
        fft128<+1>(v, lane);
#pragma unroll
        for (int k1 = 0; k1 < 4; k1++) tile[rb * 4 + k1][wl] = v[k1];
    }
    __syncthreads();
#pragma unroll
    for (int j = 0; j < 16; j++) {
        int i = t + j * 256;
        int h = i >> 5, wl = i & 31;
        g_XF[pbase + (size_t)h * 128 + w0 + wl] = tile[h][wl];
    }
}

// ---------------- K5: IFFT along W + transpose to (B,H,W,C) real out ----------------
__global__ void ifftw_out_kernel(float* __restrict__ out) {
    __shared__ float tile[128][33];
    int bh = blockIdx.y;
    int b = bh >> 7;
    int h = bh & 127;
    int c0 = blockIdx.x * 32;
    int t = threadIdx.x;
    int warp = t >> 5, lane = t & 31;
    int rb = __brev(lane) >> 27;
    const float inv = 1.0f / 16384.0f;
#pragma unroll
    for (int cc4 = 0; cc4 < 4; cc4++) {
        int cl = warp * 4 + cc4;
        size_t rowoff = (size_t)(b * CC + c0 + cl) * HW + (size_t)h * 128;
        float2 v[4];
#pragma unroll
        for (int n1 = 0; n1 < 4; n1++) v[n1] = g_XF[rowoff + n1 * 32 + lane];
        fft128<+1>(v, lane);
#pragma unroll
        for (int k1 = 0; k1 < 4; k1++) tile[rb * 4 + k1][cl] = v[k1].x * inv;
    }
    __syncthreads();
#pragma unroll
    for (int j = 0; j < 16; j++) {
        int i = t + j * 256;
        int w = i >> 5, cl = i & 31;
        out[(size_t)bh * (WD * CC) + (size_t)w * CC + c0 + cl] = tile[w][cl];
    }
}

extern "C" void kernel_launch(void* const* d_in, const int* in_sizes, int n_in,
                              void* d_out, int out_size) {
    const float* x   = (const float*)d_in[0];
    const float* Ak  = (const float*)d_in[1];
    const float* Bk  = (const float*)d_in[2];
    const float* Wma = (const float*)d_in[3];
    const float* bma = (const float*)d_in[4];
    const float* Wpa = (const float*)d_in[5];
    const float* bpa = (const float*)d_in[6];
    const float* Wmb = (const float*)d_in[7];
    const float* bmb = (const float*)d_in[8];
    const float* Wpb = (const float*)d_in[9];
    const float* bpb = (const float*)d_in[10];
    float* out = (float*)d_out;

    cudaFuncSetAttribute(gemm_mma_kernel, cudaFuncAttributeMaxDynamicSharedMemorySize, GEMM_SMEM);

    pack_kernel<<<1024, 256>>>(Wma, Wpa, Wmb, Wpb, bma, bpa, bmb, bpb);
    kfreq_kernel<<<dim3(128, 256), 128>>>(Ak, Bk);
    fftw_kernel<<<dim3(8, 1024), 256>>>(x);
    gemm_mma_kernel<<<dim3(4, 2048), 256, GEMM_SMEM>>>();
    ffth_pointwise_kernel<<<dim3(4, 2048), 256>>>();
    ifftw_out_kernel<<<dim3(8, 1024), 256>>>(out);
}

// round 15
// speedup vs baseline: 1.5893x; 1.0388x over previous
#include <cuda_runtime.h>
#include <cuda_bf16.h>
#include <cstdint>
#include <math.h>

#define BB   8
#define HD   128
#define WD   128
#define CC   256
#define HW   16384
#define NPLANE 2048
#define TWOPI 6.28318530717958647692f

// ---------------- scratch ----------------
__device__ __align__(16) float2 g_AF[CC * HW];
__device__ __align__(16) float2 g_BF[CC * HW];
__device__ __align__(16) float2 g_XF[NPLANE * HW];
__device__ __align__(16) float2 g_GA[NPLANE * HW];
__device__ __align__(16) float2 g_GB[NPLANE * HW];
__device__ __align__(16) __nv_bfloat16 g_WbHi[1024 * 256];   // [n][k], n = d*4+m
__device__ __align__(16) __nv_bfloat16 g_WbLo[1024 * 256];
__device__ __align__(16) __nv_bfloat16 g_XHi[131072 * 256];  // [pix][c] bf16 hi
__device__ __align__(16) __nv_bfloat16 g_XLo[131072 * 256];  // [pix][c] bf16 lo
__device__ float  g_bpk[1024];

// ---------------- complex helpers ----------------
__device__ __forceinline__ float2 cmul(float2 a, float2 b) {
    return make_float2(a.x * b.x - a.y * b.y, a.x * b.y + a.y * b.x);
}
__device__ __forceinline__ float2 cadd(float2 a, float2 b) { return make_float2(a.x + b.x, a.y + b.y); }
__device__ __forceinline__ float2 csub(float2 a, float2 b) { return make_float2(a.x - b.x, a.y - b.y); }
__device__ __forceinline__ float2 cconj(float2 a) { return make_float2(a.x, -a.y); }

__device__ __forceinline__ float2 shfl_xor_c(float2 v, int m) {
    float2 r;
    r.x = __shfl_xor_sync(0xffffffffu, v.x, m);
    r.y = __shfl_xor_sync(0xffffffffu, v.y, m);
    return r;
}

__device__ __forceinline__ uint32_t smem_u32(const void* p) {
    uint32_t a;
    asm("{ .reg .u64 t; cvta.to.shared.u64 t, %1; cvt.u32.u64 %0, t; }" : "=r"(a) : "l"(p));
    return a;
}
__device__ __forceinline__ void ldsm4(uint32_t* r, uint32_t addr) {
    asm volatile("ldmatrix.sync.aligned.m8n8.x4.shared.b16 {%0,%1,%2,%3}, [%4];"
                 : "=r"(r[0]), "=r"(r[1]), "=r"(r[2]), "=r"(r[3]) : "r"(addr));
}
__device__ __forceinline__ void mma16816(float* c, const uint32_t* a, const uint32_t* b) {
    asm volatile("mma.sync.aligned.m16n8k16.row.col.f32.bf16.bf16.f32 "
                 "{%0,%1,%2,%3}, {%4,%5,%6,%7}, {%8,%9}, {%0,%1,%2,%3};"
                 : "+f"(c[0]), "+f"(c[1]), "+f"(c[2]), "+f"(c[3])
                 : "r"(a[0]), "r"(a[1]), "r"(a[2]), "r"(a[3]), "r"(b[0]), "r"(b[1]));
}
__device__ __forceinline__ void cp16(uint32_t dst, const void* src) {
    asm volatile("cp.async.cg.shared.global [%0], [%1], 16;" :: "r"(dst), "l"(src) : "memory");
}
#define CP_COMMIT() asm volatile("cp.async.commit_group;" ::: "memory")
#define CP_WAIT1()  asm volatile("cp.async.wait_group 1;" ::: "memory")
#define CP_WAIT0()  asm volatile("cp.async.wait_group 0;" ::: "memory")

// 128-pt FFT: 4 regs x 32 lanes. Natural in; out reg k1 @ lane t = index 4*brev5(t)+k1.
template <int SGN>
__device__ __forceinline__ void fft128(float2 v[4], int lane) {
    float2 t0 = cadd(v[0], v[2]);
    float2 t1 = csub(v[0], v[2]);
    float2 t2 = cadd(v[1], v[3]);
    float2 t3 = csub(v[1], v[3]);
    float2 jt3 = make_float2(-t3.y, t3.x);
    float2 y0 = cadd(t0, t2);
    float2 y2 = csub(t0, t2);
    float2 y1, y3;
    if (SGN < 0) { y1 = csub(t1, jt3); y3 = cadd(t1, jt3); }
    else         { y1 = cadd(t1, jt3); y3 = csub(t1, jt3); }
    float ss, cc;
    __sincosf((float)SGN * TWOPI * (float)lane * (1.0f / 128.0f), &ss, &cc);
    float2 w1 = make_float2(cc, ss);
    float2 w2 = cmul(w1, w1);
    float2 w3 = cmul(w2, w1);
    v[0] = y0;
    v[1] = cmul(y1, w1);
    v[2] = cmul(y2, w2);
    v[3] = cmul(y3, w3);
#pragma unroll
    for (int h = 16; h >= 1; h >>= 1) {
        int j = lane & (h - 1);
        float ang = (float)SGN * TWOPI * (float)j / (float)(2 * h);
        float ws, wc;
        __sincosf(ang, &ws, &wc);
        float2 w = make_float2(wc, ws);
        bool hi = (lane & h) != 0;
#pragma unroll
        for (int k = 0; k < 4; k++) {
            float2 o = shfl_xor_c(v[k], h);
            if (hi) v[k] = cmul(csub(o, v[k]), w);
            else    v[k] = cadd(v[k], o);
        }
    }
}

// ---------------- K0: pack weights (bf16 hi/lo, [n][k]) + biases ----------------
__global__ void pack_kernel(const float* __restrict__ Wma, const float* __restrict__ Wpa,
                            const float* __restrict__ Wmb, const float* __restrict__ Wpb,
                            const float* __restrict__ bma, const float* __restrict__ bpa,
                            const float* __restrict__ bmb, const float* __restrict__ bpb) {
    int i = blockIdx.x * 256 + threadIdx.x;
    if (i < 1024 * 256) {
        int n = i >> 8, k = i & 255;
        int d = n >> 2, m = n & 3;
        const float* Wm = (m == 0) ? Wma : (m == 1) ? Wpa : (m == 2) ? Wmb : Wpb;
        float w = Wm[k * 256 + d];
        __nv_bfloat16 hi = __float2bfloat16(w);
        __nv_bfloat16 lo = __float2bfloat16(w - __bfloat162float(hi));
        g_WbHi[(size_t)n * 256 + k] = hi;
        g_WbLo[(size_t)n * 256 + k] = lo;
    }
    if (i < 1024) {
        int d = i >> 2, m = i & 3;
        const float* bv = (m == 0) ? bma : (m == 1) ? bpa : (m == 2) ? bmb : bpb;
        g_bpk[i] = bv[d];
    }
}

// ---------------- K1: freq-domain conv kernels (49-tap DFT) ----------------
__global__ void kfreq_kernel(const float* __restrict__ Ak, const float* __restrict__ Bk) {
    int w = threadIdx.x;
    int h = blockIdx.x;
    int c = blockIdx.y;
    __shared__ float ka[49], kb[49];
    if (threadIdx.x < 49) {
        ka[threadIdx.x] = Ak[c * 49 + threadIdx.x];
        kb[threadIdx.x] = Bk[c * 49 + threadIdx.x];
    }
    __syncthreads();
    float2 eh[7], ew[7];
    {
        float s, ct;
        sincosf(-TWOPI * (float)h * (1.0f / 128.0f), &s, &ct);
        float2 b1 = make_float2(ct, s);
        eh[3] = make_float2(1.f, 0.f);
        eh[4] = b1; eh[5] = cmul(b1, b1); eh[6] = cmul(eh[5], b1);
        eh[2] = cconj(eh[4]); eh[1] = cconj(eh[5]); eh[0] = cconj(eh[6]);
        sincosf(-TWOPI * (float)w * (1.0f / 128.0f), &s, &ct);
        float2 b2 = make_float2(ct, s);
        ew[3] = make_float2(1.f, 0.f);
        ew[4] = b2; ew[5] = cmul(b2, b2); ew[6] = cmul(ew[5], b2);
        ew[2] = cconj(ew[4]); ew[1] = cconj(ew[5]); ew[0] = cconj(ew[6]);
    }
    float2 accA = make_float2(0.f, 0.f), accB = make_float2(0.f, 0.f);
#pragma unroll
    for (int i = 0; i < 7; i++) {
        float2 rowA = make_float2(0.f, 0.f), rowB = make_float2(0.f, 0.f);
#pragma unroll
        for (int j = 0; j < 7; j++) {
            float va = ka[i * 7 + j], vb = kb[i * 7 + j];
            rowA.x += va * ew[j].x; rowA.y += va * ew[j].y;
            rowB.x += vb * ew[j].x; rowB.y += vb * ew[j].y;
        }
        accA = cadd(accA, cmul(eh[i], rowA));
        accB = cadd(accB, cmul(eh[i], rowB));
    }
    size_t idx = (size_t)c * HW + h * 128 + w;
    g_AF[idx] = accA;
    g_BF[idx] = accB;
}

// ---------------- K3: FFT along W + transpose to planar + bf16 split of x ----------------
__global__ void fftw_kernel(const float* __restrict__ x) {
    __shared__ float tile[128][33];
    int bh = blockIdx.y;
    int b = bh >> 7;
    int c0 = blockIdx.x * 32;
    int t = threadIdx.x;
#pragma unroll
    for (int j = 0; j < 4; j++) {
        int i = t + j * 256;                 // 0..1023 float4s
        int w = i >> 3, c4 = (i & 7) * 4;
        float4 v = *(const float4*)(x + (size_t)bh * (WD * CC) + (size_t)w * CC + c0 + c4);
        tile[w][c4 + 0] = v.x; tile[w][c4 + 1] = v.y;
        tile[w][c4 + 2] = v.z; tile[w][c4 + 3] = v.w;
        __nv_bfloat16 h0 = __float2bfloat16(v.x), h1 = __float2bfloat16(v.y);
        __nv_bfloat16 h2 = __float2bfloat16(v.z), h3 = __float2bfloat16(v.w);
        __nv_bfloat16 l0 = __float2bfloat16(v.x - __bfloat162float(h0));
        __nv_bfloat16 l1 = __float2bfloat16(v.y - __bfloat162float(h1));
        __nv_bfloat16 l2 = __float2bfloat16(v.z - __bfloat162float(h2));
        __nv_bfloat16 l3 = __float2bfloat16(v.w - __bfloat162float(h3));
        size_t pi = ((size_t)bh * 128 + w) * 256 + c0 + c4;
        __nv_bfloat162 ph01, ph23, pl01, pl23;
        ph01.x = h0; ph01.y = h1; ph23.x = h2; ph23.y = h3;
        pl01.x = l0; pl01.y = l1; pl23.x = l2; pl23.y = l3;
        uint2 uh, ul;
        uh.x = *reinterpret_cast<uint32_t*>(&ph01); uh.y = *reinterpret_cast<uint32_t*>(&ph23);
        ul.x = *reinterpret_cast<uint32_t*>(&pl01); ul.y = *reinterpret_cast<uint32_t*>(&pl23);
        *(uint2*)(g_XHi + pi) = uh;
        *(uint2*)(g_XLo + pi) = ul;
    }
    __syncthreads();
    int warp = t >> 5, lane = t & 31;
    int rb = __brev(lane) >> 27;
    int h = bh & 127;
#pragma unroll
    for (int cc4 = 0; cc4 < 4; cc4++) {
        int cl = warp * 4 + cc4;
        float2 v[4];
#pragma unroll
        for (int n1 = 0; n1 < 4; n1++) v[n1] = make_float2(tile[n1 * 32 + lane][cl], 0.f);
        fft128<-1>(v, lane);
        size_t rowoff = (size_t)(b * CC + c0 + cl) * HW + (size_t)h * 128 + rb * 4;
        *(float4*)(g_XF + rowoff)     = make_float4(v[0].x, v[0].y, v[1].x, v[1].y);
        *(float4*)(g_XF + rowoff + 2) = make_float4(v[2].x, v[2].y, v[3].x, v[3].y);
    }
}

// ---------------- K2: HMMA GEMM, 64x256 tile, A double-buffered, 2 CTAs/SM ----------------
// K=256 in 4 chunks of 64; A: 2 bufs x (hi+lo) 9216B; B: single (hi+lo) 36864B each.
#define STRD 144                              // 72 elems * 2B row stride
#define A_BYTES 9216
#define OFF_AH0 0
#define OFF_AL0 9216
#define OFF_AH1 18432
#define OFF_AL1 27648
#define OFF_BH  36864
#define OFF_BL  73728
#define GEMM_SMEM 110592                      // 108 KB; Z tile (256*66*4=67584) aliases
#define Z_STRIDE 66

__device__ __forceinline__ void issueA(uint32_t sb, size_t pixbase, int kc, int tid) {
    uint32_t ah = sb + ((kc & 1) ? OFF_AH1 : OFF_AH0);
    uint32_t al = sb + ((kc & 1) ? OFF_AL1 : OFF_AL0);
    int u = tid << 1;                         // 2 consecutive 16B segs, same row
    int row = u >> 3, seg = u & 7;
    size_t gofs = (pixbase + row) * 256 + kc * 64 + seg * 8;
    uint32_t d = (uint32_t)(row * STRD + seg * 16);
    cp16(ah + d,      g_XHi + gofs);
    cp16(ah + d + 16, g_XHi + gofs + 8);
    cp16(al + d,      g_XLo + gofs);
    cp16(al + d + 16, g_XLo + gofs + 8);
}

__global__ __launch_bounds__(256, 2) void gemm_mma_kernel() {
    extern __shared__ char smem[];
    uint32_t sb = smem_u32(smem);
    int tid = threadIdx.x;
    int lane = tid & 31, warp = tid >> 5;
    int wm = warp >> 2, wn = warp & 3;
    int n0 = blockIdx.x * 256;
    size_t pixbase = (size_t)blockIdx.y * 64;

    float acc[2][8][4];
#pragma unroll
    for (int i = 0; i < 2; i++)
#pragma unroll
        for (int j = 0; j < 8; j++)
#pragma unroll
            for (int k = 0; k < 4; k++) acc[i][j][k] = 0.f;

    int sub = lane >> 3, l7 = lane & 7;
    int a_r = ((sub & 1) << 3) + l7;
    int a_k = (sub >> 1) << 3;
    int b_r = ((sub >> 1) << 3) + l7;
    int b_k = (sub & 1) << 3;

    issueA(sb, pixbase, 0, tid);
    CP_COMMIT();

#pragma unroll
    for (int kc = 0; kc < 4; kc++) {
        __syncthreads();                      // guard B buffer + alt-A buffer reuse
        // B chunk kc: 256 rows x 64 k (hi+lo)
#pragma unroll
        for (int it = 0; it < 8; it++) {
            int u = tid + it * 256;
            int row = u >> 3, seg = u & 7;
            size_t gofs = (size_t)(n0 + row) * 256 + kc * 64 + seg * 8;
            uint32_t d = (uint32_t)(row * STRD + seg * 16);
            cp16(sb + OFF_BH + d, g_WbHi + gofs);
            cp16(sb + OFF_BL + d, g_WbLo + gofs);
        }
        CP_COMMIT();
        if (kc < 3) {
            issueA(sb, pixbase, kc + 1, tid); // prefetch next A (DRAM) across this compute
            CP_COMMIT();
            CP_WAIT1();                       // A(kc), B(kc) done; A(kc+1) in flight
        } else {
            CP_WAIT0();
        }
        __syncthreads();

        uint32_t ah_base = sb + ((kc & 1) ? OFF_AH1 : OFF_AH0);
        uint32_t al_base = sb + ((kc & 1) ? OFF_AL1 : OFF_AL0);
#pragma unroll
        for (int ks = 0; ks < 4; ks++) {
            uint32_t ah[2][4], al[2][4];
#pragma unroll
            for (int mt = 0; mt < 2; mt++) {
                uint32_t aoff = (uint32_t)((wm * 32 + mt * 16 + a_r) * STRD + (ks * 16 + a_k) * 2);
                ldsm4(ah[mt], ah_base + aoff);
                ldsm4(al[mt], al_base + aoff);
            }
#pragma unroll
            for (int ntp = 0; ntp < 4; ntp++) {
                uint32_t bh[4], bl[4];
                uint32_t boff = (uint32_t)((wn * 64 + ntp * 16 + b_r) * STRD + (ks * 16 + b_k) * 2);
                ldsm4(bh, sb + OFF_BH + boff);
                ldsm4(bl, sb + OFF_BL + boff);
#pragma unroll
                for (int mt = 0; mt < 2; mt++) {
                    mma16816(acc[mt][2 * ntp],     ah[mt], bh);
                    mma16816(acc[mt][2 * ntp + 1], ah[mt], bh + 2);
                    mma16816(acc[mt][2 * ntp],     ah[mt], bl);
                    mma16816(acc[mt][2 * ntp + 1], ah[mt], bl + 2);
                    mma16816(acc[mt][2 * ntp],     al[mt], bh);
                    mma16816(acc[mt][2 * ntp + 1], al[mt], bh + 2);
                }
            }
        }
    }

    // ---- epilogue: Z (transposed, 256 cols x 64 rows) in SMEM, then gates ----
    __syncthreads();
    float* zs = (float*)smem;
    {
        int r0 = wm * 32 + (lane >> 2);
        int c0 = wn * 64 + 2 * (lane & 3);
#pragma unroll
        for (int mt = 0; mt < 2; mt++)
#pragma unroll
            for (int nt = 0; nt < 8; nt++) {
                int rr = r0 + mt * 16;
                int cc = c0 + nt * 8;
                zs[cc * Z_STRIDE + rr]           = acc[mt][nt][0];
                zs[(cc + 1) * Z_STRIDE + rr]     = acc[mt][nt][1];
                zs[cc * Z_STRIDE + rr + 8]       = acc[mt][nt][2];
                zs[(cc + 1) * Z_STRIDE + rr + 8] = acc[mt][nt][3];
            }
    }
    __syncthreads();
    {
        int pr = tid & 63;
        int dgrp = tid >> 6;                  // 0..3
        int pix = (int)pixbase + pr;
        int b = pix >> 14;
        int hw = pix & 16383;
#pragma unroll 1
        for (int it = 0; it < 16; it++) {
            int dl = dgrp + it * 4;           // 0..63
            int e0 = dl * 4;
            float zma = zs[e0 * Z_STRIDE + pr]       + g_bpk[n0 + e0];
            float zpa = zs[(e0 + 1) * Z_STRIDE + pr] + g_bpk[n0 + e0 + 1];
            float zmb = zs[(e0 + 2) * Z_STRIDE + pr] + g_bpk[n0 + e0 + 2];
            float zpb = zs[(e0 + 3) * Z_STRIDE + pr] + g_bpk[n0 + e0 + 3];
            float ma  = 1.0f / (1.0f + __expf(-zma));
            float mbg = 1.0f / (1.0f + __expf(-zmb));
            float sa, ca, sbp, cb;
            __sincosf(zpa, &sa, &ca);
            __sincosf(zpb, &sbp, &cb);
            int d = (n0 >> 2) + dl;
            size_t po = (size_t)(b * 256 + d) * HW + hw;
            g_GA[po] = make_float2(ma * ca, ma * sa);
            g_GB[po] = make_float2(mbg * cb, mbg * sbp);
        }
    }
}

// ---------------- K4: FFT-H + pointwise recurrence + IFFT-H ----------------
__global__ void ffth_pointwise_kernel() {
    __shared__ float2 tile[128][33];
    int plane = blockIdx.y;
    int c = plane & 255;
    int w0 = blockIdx.x * 32;
    int t = threadIdx.x;
    size_t pbase = (size_t)plane * HW;
    size_t cbase = (size_t)c * HW;
#pragma unroll
    for (int j = 0; j < 8; j++) {
        int p = t + j * 256;                  // 0..2047 float2-pairs
        int h = p >> 4, wl = (p & 15) * 2;
        float4 v = *(const float4*)(g_XF + pbase + (size_t)h * 128 + w0 + wl);
        tile[h][wl]     = make_float2(v.x, v.y);
        tile[h][wl + 1] = make_float2(v.z, v.w);
    }
    __syncthreads();
    int warp = t >> 5, lane = t & 31;
    int rb = __brev(lane) >> 27;
#pragma unroll
    for (int cc4 = 0; cc4 < 4; cc4++) {
        int wl = warp * 4 + cc4;
        float2 v[4];
#pragma unroll
        for (int n1 = 0; n1 < 4; n1++) v[n1] = tile[n1 * 32 + lane][wl];
        fft128<-1>(v, lane);
#pragma unroll
        for (int k1 = 0; k1 < 4; k1++) tile[rb * 4 + k1][wl] = v[k1];
    }
    __syncthreads();
#pragma unroll
    for (int j = 0; j < 8; j++) {
        int p = t + j * 256;
        int h = p >> 4, wl = (p & 15) * 2;
        size_t off = (size_t)h * 128 + w0 + wl;
        float4 gav = *(const float4*)(g_GA + pbase + off);
        float4 gbv = *(const float4*)(g_GB + pbase + off);
        float4 afv = *(const float4*)(g_AF + cbase + off);
        float4 bfv = *(const float4*)(g_BF + cbase + off);
#pragma unroll
        for (int e = 0; e < 2; e++) {
            float2 xf = tile[h][wl + e];
            float2 ga = e ? make_float2(gav.z, gav.w) : make_float2(gav.x, gav.y);
            float2 gb = e ? make_float2(gbv.z, gbv.w) : make_float2(gbv.x, gbv.y);
            float2 af = e ? make_float2(afv.z, afv.w) : make_float2(afv.x, afv.y);
            float2 bf = e ? make_float2(bfv.z, bfv.w) : make_float2(bfv.x, bfv.y);
            float2 a  = cmul(ga, af);
            float2 bb = cmul(cmul(gb, bf), xf);
            float2 a2 = cmul(a, a);
            float2 a4 = cmul(a2, a2);
            float2 p1 = make_float2(1.f + a.x,  a.y);
            float2 p2 = make_float2(1.f + a2.x, a2.y);
            float2 p4 = make_float2(1.f + a4.x, a4.y);
            tile[h][wl + e] = cmul(bb, cmul(cmul(p1, p2), p4));
        }
    }
    __syncthreads();
#pragma unroll
    for (int cc4 = 0; cc4 < 4; cc4++) {
        int wl = warp * 4 + cc4;
        float2 v[4];
#pragma unroll
        for (int n1 = 0; n1 < 4; n1++) v[n1] = tile[n1 * 32 + lane][wl];
        fft128<+1>(v, lane);
#pragma unroll
        for (int k1 = 0; k1 < 4; k1++) tile[rb * 4 + k1][wl] = v[k1];
    }
    __syncthreads();
#pragma unroll
    for (int j = 0; j < 8; j++) {
        int p = t + j * 256;
        int h = p >> 4, wl = (p & 15) * 2;
        float2 a0 = tile[h][wl], a1 = tile[h][wl + 1];
        *(float4*)(g_XF + pbase + (size_t)h * 128 + w0 + wl) = make_float4(a0.x, a0.y, a1.x, a1.y);
    }
}

// ---------------- K5: IFFT along W + transpose to (B,H,W,C) real out ----------------
__global__ void ifftw_out_kernel(float* __restrict__ out) {
    __shared__ float tile[128][33];
    int bh = blockIdx.y;
    int b = bh >> 7;
    int h = bh & 127;
    int c0 = blockIdx.x * 32;
    int t = threadIdx.x;
    int warp = t >> 5, lane = t & 31;
    int rb = __brev(lane) >> 27;
    const float inv = 1.0f / 16384.0f;
#pragma unroll
    for (int cc4 = 0; cc4 < 4; cc4++) {
        int cl = warp * 4 + cc4;
        size_t rowoff = (size_t)(b * CC + c0 + cl) * HW + (size_t)h * 128;
        float2 v[4];
#pragma unroll
        for (int n1 = 0; n1 < 4; n1++) v[n1] = g_XF[rowoff + n1 * 32 + lane];
        fft128<+1>(v, lane);
#pragma unroll
        for (int k1 = 0; k1 < 4; k1++) tile[rb * 4 + k1][cl] = v[k1].x * inv;
    }
    __syncthreads();
#pragma unroll
    for (int j = 0; j < 4; j++) {
        int i = t + j * 256;                 // 0..1023 float4s
        int w = i >> 3, c4 = (i & 7) * 4;
        float4 v = make_float4(tile[w][c4], tile[w][c4 + 1], tile[w][c4 + 2], tile[w][c4 + 3]);
        *(float4*)(out + (size_t)bh * (WD * CC) + (size_t)w * CC + c0 + c4) = v;
    }
}

extern "C" void kernel_launch(void* const* d_in, const int* in_sizes, int n_in,
                              void* d_out, int out_size) {
    const float* x   = (const float*)d_in[0];
    const float* Ak  = (const float*)d_in[1];
    const float* Bk  = (const float*)d_in[2];
    const float* Wma = (const float*)d_in[3];
    const float* bma = (const float*)d_in[4];
    const float* Wpa = (const float*)d_in[5];
    const float* bpa = (const float*)d_in[6];
    const float* Wmb = (const float*)d_in[7];
    const float* bmb = (const float*)d_in[8];
    const float* Wpb = (const float*)d_in[9];
    const float* bpb = (const float*)d_in[10];
    float* out = (float*)d_out;

    cudaFuncSetAttribute(gemm_mma_kernel, cudaFuncAttributeMaxDynamicSharedMemorySize, GEMM_SMEM);

    pack_kernel<<<1024, 256>>>(Wma, Wpa, Wmb, Wpb, bma, bpa, bmb, bpb);
    kfreq_kernel<<<dim3(128, 256), 128>>>(Ak, Bk);
    fftw_kernel<<<dim3(8, 1024), 256>>>(x);
    gemm_mma_kernel<<<dim3(4, 2048), 256, GEMM_SMEM>>>();
    ffth_pointwise_kernel<<<dim3(4, 2048), 256>>>();
    ifftw_out_kernel<<<dim3(8, 1024), 256>>>(out);
}

// round 16
// speedup vs baseline: 1.6103x; 1.0132x over previous
#include <cuda_runtime.h>
#include <cuda_bf16.h>
#include <cstdint>
#include <math.h>

#define BB   8
#define HD   128
#define WD   128
#define CC   256
#define HW   16384
#define NPLANE 2048
#define TWOPI 6.28318530717958647692f

// ---------------- scratch ----------------
__device__ __align__(16) float2 g_AF[CC * HW];
__device__ __align__(16) float2 g_BF[CC * HW];
__device__ __align__(16) float2 g_XF[NPLANE * HW];
__device__ __align__(16) float2 g_GA[NPLANE * HW];
__device__ __align__(16) float2 g_GB[NPLANE * HW];
__device__ __align__(16) __nv_bfloat16 g_WbHi[1024 * 256];   // [n][k], n = d*4+m
__device__ __align__(16) __nv_bfloat16 g_WbLo[1024 * 256];
__device__ __align__(16) __nv_bfloat16 g_XHi[131072 * 256];  // [pix][c] bf16 hi
__device__ __align__(16) __nv_bfloat16 g_XLo[131072 * 256];  // [pix][c] bf16 lo
__device__ float  g_bpk[1024];

// ---------------- complex helpers ----------------
__device__ __forceinline__ float2 cmul(float2 a, float2 b) {
    return make_float2(a.x * b.x - a.y * b.y, a.x * b.y + a.y * b.x);
}
__device__ __forceinline__ float2 cadd(float2 a, float2 b) { return make_float2(a.x + b.x, a.y + b.y); }
__device__ __forceinline__ float2 csub(float2 a, float2 b) { return make_float2(a.x - b.x, a.y - b.y); }
__device__ __forceinline__ float2 cconj(float2 a) { return make_float2(a.x, -a.y); }

__device__ __forceinline__ float2 shfl_xor_c(float2 v, int m) {
    float2 r;
    r.x = __shfl_xor_sync(0xffffffffu, v.x, m);
    r.y = __shfl_xor_sync(0xffffffffu, v.y, m);
    return r;
}

__device__ __forceinline__ uint32_t smem_u32(const void* p) {
    uint32_t a;
    asm("{ .reg .u64 t; cvta.to.shared.u64 t, %1; cvt.u32.u64 %0, t; }" : "=r"(a) : "l"(p));
    return a;
}
__device__ __forceinline__ void ldsm4(uint32_t* r, uint32_t addr) {
    asm volatile("ldmatrix.sync.aligned.m8n8.x4.shared.b16 {%0,%1,%2,%3}, [%4];"
                 : "=r"(r[0]), "=r"(r[1]), "=r"(r[2]), "=r"(r[3]) : "r"(addr));
}
__device__ __forceinline__ void mma16816(float* c, const uint32_t* a, const uint32_t* b) {
    asm volatile("mma.sync.aligned.m16n8k16.row.col.f32.bf16.bf16.f32 "
                 "{%0,%1,%2,%3}, {%4,%5,%6,%7}, {%8,%9}, {%0,%1,%2,%3};"
                 : "+f"(c[0]), "+f"(c[1]), "+f"(c[2]), "+f"(c[3])
                 : "r"(a[0]), "r"(a[1]), "r"(a[2]), "r"(a[3]), "r"(b[0]), "r"(b[1]));
}
__device__ __forceinline__ void cp16(uint32_t dst, const void* src) {
    asm volatile("cp.async.cg.shared.global [%0], [%1], 16;" :: "r"(dst), "l"(src) : "memory");
}
#define CP_COMMIT() asm volatile("cp.async.commit_group;" ::: "memory")
#define CP_WAIT0()  asm volatile("cp.async.wait_group 0;" ::: "memory")

// 128-pt FFT: 4 regs x 32 lanes. Natural in; out reg k1 @ lane t = index 4*brev5(t)+k1.
template <int SGN>
__device__ __forceinline__ void fft128(float2 v[4], int lane) {
    float2 t0 = cadd(v[0], v[2]);
    float2 t1 = csub(v[0], v[2]);
    float2 t2 = cadd(v[1], v[3]);
    float2 t3 = csub(v[1], v[3]);
    float2 jt3 = make_float2(-t3.y, t3.x);
    float2 y0 = cadd(t0, t2);
    float2 y2 = csub(t0, t2);
    float2 y1, y3;
    if (SGN < 0) { y1 = csub(t1, jt3); y3 = cadd(t1, jt3); }
    else         { y1 = cadd(t1, jt3); y3 = csub(t1, jt3); }
    float ss, cc;
    __sincosf((float)SGN * TWOPI * (float)lane * (1.0f / 128.0f), &ss, &cc);
    float2 w1 = make_float2(cc, ss);
    float2 w2 = cmul(w1, w1);
    float2 w3 = cmul(w2, w1);
    v[0] = y0;
    v[1] = cmul(y1, w1);
    v[2] = cmul(y2, w2);
    v[3] = cmul(y3, w3);
#pragma unroll
    for (int h = 16; h >= 1; h >>= 1) {
        int j = lane & (h - 1);
        float ang = (float)SGN * TWOPI * (float)j / (float)(2 * h);
        float ws, wc;
        __sincosf(ang, &ws, &wc);
        float2 w = make_float2(wc, ws);
        bool hi = (lane & h) != 0;
#pragma unroll
        for (int k = 0; k < 4; k++) {
            float2 o = shfl_xor_c(v[k], h);
            if (hi) v[k] = cmul(csub(o, v[k]), w);
            else    v[k] = cadd(v[k], o);
        }
    }
}

// ---------------- K0: pack weights (bf16 hi/lo, [n][k]) + biases ----------------
__global__ void pack_kernel(const float* __restrict__ Wma, const float* __restrict__ Wpa,
                            const float* __restrict__ Wmb, const float* __restrict__ Wpb,
                            const float* __restrict__ bma, const float* __restrict__ bpa,
                            const float* __restrict__ bmb, const float* __restrict__ bpb) {
    int i = blockIdx.x * 256 + threadIdx.x;
    if (i < 1024 * 256) {
        int n = i >> 8, k = i & 255;
        int d = n >> 2, m = n & 3;
        const float* Wm = (m == 0) ? Wma : (m == 1) ? Wpa : (m == 2) ? Wmb : Wpb;
        float w = Wm[k * 256 + d];
        __nv_bfloat16 hi = __float2bfloat16(w);
        __nv_bfloat16 lo = __float2bfloat16(w - __bfloat162float(hi));
        g_WbHi[(size_t)n * 256 + k] = hi;
        g_WbLo[(size_t)n * 256 + k] = lo;
    }
    if (i < 1024) {
        int d = i >> 2, m = i & 3;
        const float* bv = (m == 0) ? bma : (m == 1) ? bpa : (m == 2) ? bmb : bpb;
        g_bpk[i] = bv[d];
    }
}

// ---------------- K1: freq-domain conv kernels (49-tap DFT) ----------------
__global__ void kfreq_kernel(const float* __restrict__ Ak, const float* __restrict__ Bk) {
    int w = threadIdx.x;
    int h = blockIdx.x;
    int c = blockIdx.y;
    __shared__ float ka[49], kb[49];
    if (threadIdx.x < 49) {
        ka[threadIdx.x] = Ak[c * 49 + threadIdx.x];
        kb[threadIdx.x] = Bk[c * 49 + threadIdx.x];
    }
    __syncthreads();
    float2 eh[7], ew[7];
    {
        float s, ct;
        sincosf(-TWOPI * (float)h * (1.0f / 128.0f), &s, &ct);
        float2 b1 = make_float2(ct, s);
        eh[3] = make_float2(1.f, 0.f);
        eh[4] = b1; eh[5] = cmul(b1, b1); eh[6] = cmul(eh[5], b1);
        eh[2] = cconj(eh[4]); eh[1] = cconj(eh[5]); eh[0] = cconj(eh[6]);
        sincosf(-TWOPI * (float)w * (1.0f / 128.0f), &s, &ct);
        float2 b2 = make_float2(ct, s);
        ew[3] = make_float2(1.f, 0.f);
        ew[4] = b2; ew[5] = cmul(b2, b2); ew[6] = cmul(ew[5], b2);
        ew[2] = cconj(ew[4]); ew[1] = cconj(ew[5]); ew[0] = cconj(ew[6]);
    }
    float2 accA = make_float2(0.f, 0.f), accB = make_float2(0.f, 0.f);
#pragma unroll
    for (int i = 0; i < 7; i++) {
        float2 rowA = make_float2(0.f, 0.f), rowB = make_float2(0.f, 0.f);
#pragma unroll
        for (int j = 0; j < 7; j++) {
            float va = ka[i * 7 + j], vb = kb[i * 7 + j];
            rowA.x += va * ew[j].x; rowA.y += va * ew[j].y;
            rowB.x += vb * ew[j].x; rowB.y += vb * ew[j].y;
        }
        accA = cadd(accA, cmul(eh[i], rowA));
        accB = cadd(accB, cmul(eh[i], rowB));
    }
    size_t idx = (size_t)c * HW + h * 128 + w;
    g_AF[idx] = accA;
    g_BF[idx] = accB;
}

// ---------------- K3: FFT along W + transpose to planar + bf16 split of x ----------------
__global__ void fftw_kernel(const float* __restrict__ x) {
    __shared__ float tile[128][33];
    int bh = blockIdx.y;
    int b = bh >> 7;
    int c0 = blockIdx.x * 32;
    int t = threadIdx.x;
#pragma unroll
    for (int j = 0; j < 4; j++) {
        int i = t + j * 256;                 // 0..1023 float4s
        int w = i >> 3, c4 = (i & 7) * 4;
        float4 v = *(const float4*)(x + (size_t)bh * (WD * CC) + (size_t)w * CC + c0 + c4);
        tile[w][c4 + 0] = v.x; tile[w][c4 + 1] = v.y;
        tile[w][c4 + 2] = v.z; tile[w][c4 + 3] = v.w;
        __nv_bfloat16 h0 = __float2bfloat16(v.x), h1 = __float2bfloat16(v.y);
        __nv_bfloat16 h2 = __float2bfloat16(v.z), h3 = __float2bfloat16(v.w);
        __nv_bfloat16 l0 = __float2bfloat16(v.x - __bfloat162float(h0));
        __nv_bfloat16 l1 = __float2bfloat16(v.y - __bfloat162float(h1));
        __nv_bfloat16 l2 = __float2bfloat16(v.z - __bfloat162float(h2));
        __nv_bfloat16 l3 = __float2bfloat16(v.w - __bfloat162float(h3));
        size_t pi = ((size_t)bh * 128 + w) * 256 + c0 + c4;
        __nv_bfloat162 ph01, ph23, pl01, pl23;
        ph01.x = h0; ph01.y = h1; ph23.x = h2; ph23.y = h3;
        pl01.x = l0; pl01.y = l1; pl23.x = l2; pl23.y = l3;
        uint2 uh, ul;
        uh.x = *reinterpret_cast<uint32_t*>(&ph01); uh.y = *reinterpret_cast<uint32_t*>(&ph23);
        ul.x = *reinterpret_cast<uint32_t*>(&pl01); ul.y = *reinterpret_cast<uint32_t*>(&pl23);
        *(uint2*)(g_XHi + pi) = uh;
        *(uint2*)(g_XLo + pi) = ul;
    }
    __syncthreads();
    int warp = t >> 5, lane = t & 31;
    int rb = __brev(lane) >> 27;
    int h = bh & 127;
#pragma unroll
    for (int cc4 = 0; cc4 < 4; cc4++) {
        int cl = warp * 4 + cc4;
        float2 v[4];
#pragma unroll
        for (int n1 = 0; n1 < 4; n1++) v[n1] = make_float2(tile[n1 * 32 + lane][cl], 0.f);
        fft128<-1>(v, lane);
        size_t rowoff = (size_t)(b * CC + c0 + cl) * HW + (size_t)h * 128 + rb * 4;
        *(float4*)(g_XF + rowoff)     = make_float4(v[0].x, v[0].y, v[1].x, v[1].y);
        *(float4*)(g_XF + rowoff + 2) = make_float4(v[2].x, v[2].y, v[3].x, v[3].y);
    }
}

// ---------------- K2: HMMA GEMM, 64x256 tile, serial chunks, dep-4 MMA order, 2 CTAs/SM ----------------
#define STRD 144                              // 72 elems * 2B row stride
#define OFF_AH 0
#define OFF_AL 9216
#define OFF_BH 18432
#define OFF_BL 55296
#define GEMM_SMEM 92160                       // 90 KB; Z tile (256*66*4=67584) aliases
#define Z_STRIDE 66

__global__ __launch_bounds__(256, 2) void gemm_mma_kernel() {
    extern __shared__ char smem[];
    uint32_t sb = smem_u32(smem);
    int tid = threadIdx.x;
    int lane = tid & 31, warp = tid >> 5;
    int wm = warp >> 2, wn = warp & 3;
    int n0 = blockIdx.x * 256;
    size_t pixbase = (size_t)blockIdx.y * 64;

    float acc[2][8][4];
#pragma unroll
    for (int i = 0; i < 2; i++)
#pragma unroll
        for (int j = 0; j < 8; j++)
#pragma unroll
            for (int k = 0; k < 4; k++) acc[i][j][k] = 0.f;

    int sub = lane >> 3, l7 = lane & 7;
    int a_r = ((sub & 1) << 3) + l7;
    int a_k = (sub >> 1) << 3;
    int b_r = ((sub >> 1) << 3) + l7;
    int b_k = (sub & 1) << 3;

#pragma unroll
    for (int kc = 0; kc < 4; kc++) {
        __syncthreads();                      // buffer reuse guard
        // A: 64 rows x 64 k (hi+lo)
        {
            int u = tid << 1;
            int row = u >> 3, seg = u & 7;
            size_t gofs = (pixbase + row) * 256 + kc * 64 + seg * 8;
            uint32_t d = (uint32_t)(row * STRD + seg * 16);
            cp16(sb + OFF_AH + d,      g_XHi + gofs);
            cp16(sb + OFF_AH + d + 16, g_XHi + gofs + 8);
            cp16(sb + OFF_AL + d,      g_XLo + gofs);
            cp16(sb + OFF_AL + d + 16, g_XLo + gofs + 8);
        }
        // B: 256 rows x 64 k (hi+lo)
#pragma unroll
        for (int it = 0; it < 8; it++) {
            int u = tid + it * 256;
            int row = u >> 3, seg = u & 7;
            size_t gofs = (size_t)(n0 + row) * 256 + kc * 64 + seg * 8;
            uint32_t d = (uint32_t)(row * STRD + seg * 16);
            cp16(sb + OFF_BH + d, g_WbHi + gofs);
            cp16(sb + OFF_BL + d, g_WbLo + gofs);
        }
        CP_COMMIT();
        CP_WAIT0();
        __syncthreads();

#pragma unroll
        for (int ks = 0; ks < 4; ks++) {
            uint32_t ah[2][4], al[2][4];
#pragma unroll
            for (int mt = 0; mt < 2; mt++) {
                uint32_t aoff = (uint32_t)((wm * 32 + mt * 16 + a_r) * STRD + (ks * 16 + a_k) * 2);
                ldsm4(ah[mt], sb + OFF_AH + aoff);
                ldsm4(al[mt], sb + OFF_AL + aoff);
            }
#pragma unroll
            for (int ntp = 0; ntp < 4; ntp++) {
                uint32_t bh[4], bl[4];
                uint32_t boff = (uint32_t)((wn * 64 + ntp * 16 + b_r) * STRD + (ks * 16 + b_k) * 2);
                ldsm4(bh, sb + OFF_BH + boff);
                ldsm4(bl, sb + OFF_BL + boff);
                // term-major ordering: each accumulator revisited at distance 4
                mma16816(acc[0][2 * ntp],     ah[0], bh);
                mma16816(acc[0][2 * ntp + 1], ah[0], bh + 2);
                mma16816(acc[1][2 * ntp],     ah[1], bh);
                mma16816(acc[1][2 * ntp + 1], ah[1], bh + 2);
                mma16816(acc[0][2 * ntp],     ah[0], bl);
                mma16816(acc[0][2 * ntp + 1], ah[0], bl + 2);
                mma16816(acc[1][2 * ntp],     ah[1], bl);
                mma16816(acc[1][2 * ntp + 1], ah[1], bl + 2);
                mma16816(acc[0][2 * ntp],     al[0], bh);
                mma16816(acc[0][2 * ntp + 1], al[0], bh + 2);
                mma16816(acc[1][2 * ntp],     al[1], bh);
                mma16816(acc[1][2 * ntp + 1], al[1], bh + 2);
            }
        }
    }

    // ---- epilogue: Z (transposed, 256 cols x 64 rows) in SMEM, then gates ----
    __syncthreads();
    float* zs = (float*)smem;
    {
        int r0 = wm * 32 + (lane >> 2);
        int c0 = wn * 64 + 2 * (lane & 3);
#pragma unroll
        for (int mt = 0; mt < 2; mt++)
#pragma unroll
            for (int nt = 0; nt < 8; nt++) {
                int rr = r0 + mt * 16;
                int cc = c0 + nt * 8;
                zs[cc * Z_STRIDE + rr]           = acc[mt][nt][0];
                zs[(cc + 1) * Z_STRIDE + rr]     = acc[mt][nt][1];
                zs[cc * Z_STRIDE + rr + 8]       = acc[mt][nt][2];
                zs[(cc + 1) * Z_STRIDE + rr + 8] = acc[mt][nt][3];
            }
    }
    __syncthreads();
    {
        int pr = tid & 63;
        int dgrp = tid >> 6;                  // 0..3
        int pix = (int)pixbase + pr;
        int b = pix >> 14;
        int hw = pix & 16383;
#pragma unroll 1
        for (int it = 0; it < 16; it++) {
            int dl = dgrp + it * 4;           // 0..63
            int e0 = dl * 4;
            float zma = zs[e0 * Z_STRIDE + pr]       + g_bpk[n0 + e0];
            float zpa = zs[(e0 + 1) * Z_STRIDE + pr] + g_bpk[n0 + e0 + 1];
            float zmb = zs[(e0 + 2) * Z_STRIDE + pr] + g_bpk[n0 + e0 + 2];
            float zpb = zs[(e0 + 3) * Z_STRIDE + pr] + g_bpk[n0 + e0 + 3];
            float ma  = 1.0f / (1.0f + __expf(-zma));
            float mbg = 1.0f / (1.0f + __expf(-zmb));
            float sa, ca, sbp, cb;
            __sincosf(zpa, &sa, &ca);
            __sincosf(zpb, &sbp, &cb);
            int d = (n0 >> 2) + dl;
            size_t po = (size_t)(b * 256 + d) * HW + hw;
            g_GA[po] = make_float2(ma * ca, ma * sa);
            g_GB[po] = make_float2(mbg * cb, mbg * sbp);
        }
    }
}

// ---------------- K4: FFT-H + pointwise recurrence + IFFT-H ----------------
__global__ void ffth_pointwise_kernel() {
    __shared__ float2 tile[128][33];
    int plane = blockIdx.y;
    int c = plane & 255;
    int w0 = blockIdx.x * 32;
    int t = threadIdx.x;
    size_t pbase = (size_t)plane * HW;
    size_t cbase = (size_t)c * HW;
#pragma unroll
    for (int j = 0; j < 8; j++) {
        int p = t + j * 256;                  // 0..2047 float2-pairs
        int h = p >> 4, wl = (p & 15) * 2;
        float4 v = *(const float4*)(g_XF + pbase + (size_t)h * 128 + w0 + wl);
        tile[h][wl]     = make_float2(v.x, v.y);
        tile[h][wl + 1] = make_float2(v.z, v.w);
    }
    __syncthreads();
    int warp = t >> 5, lane = t & 31;
    int rb = __brev(lane) >> 27;
#pragma unroll
    for (int cc4 = 0; cc4 < 4; cc4++) {
        int wl = warp * 4 + cc4;
        float2 v[4];
#pragma unroll
        for (int n1 = 0; n1 < 4; n1++) v[n1] = tile[n1 * 32 + lane][wl];
        fft128<-1>(v, lane);
#pragma unroll
        for (int k1 = 0; k1 < 4; k1++) tile[rb * 4 + k1][wl] = v[k1];
    }
    __syncthreads();
#pragma unroll
    for (int j = 0; j < 8; j++) {
        int p = t + j * 256;
        int h = p >> 4, wl = (p & 15) * 2;
        size_t off = (size_t)h * 128 + w0 + wl;
        float4 gav = *(const float4*)(g_GA + pbase + off);
        float4 gbv = *(const float4*)(g_GB + pbase + off);
        float4 afv = *(const float4*)(g_AF + cbase + off);
        float4 bfv = *(const float4*)(g_BF + cbase + off);
#pragma unroll
        for (int e = 0; e < 2; e++) {
            float2 xf = tile[h][wl + e];
            float2 ga = e ? make_float2(gav.z, gav.w) : make_float2(gav.x, gav.y);
            float2 gb = e ? make_float2(gbv.z, gbv.w) : make_float2(gbv.x, gbv.y);
            float2 af = e ? make_float2(afv.z, afv.w) : make_float2(afv.x, afv.y);
            float2 bf = e ? make_float2(bfv.z, bfv.w) : make_float2(bfv.x, bfv.y);
            float2 a  = cmul(ga, af);
            float2 bb = cmul(cmul(gb, bf), xf);
            float2 a2 = cmul(a, a);
            float2 a4 = cmul(a2, a2);
            float2 p1 = make_float2(1.f + a.x,  a.y);
            float2 p2 = make_float2(1.f + a2.x, a2.y);
            float2 p4 = make_float2(1.f + a4.x, a4.y);
            tile[h][wl + e] = cmul(bb, cmul(cmul(p1, p2), p4));
        }
    }
    __syncthreads();
#pragma unroll
    for (int cc4 = 0; cc4 < 4; cc4++) {
        int wl = warp * 4 + cc4;
        float2 v[4];
#pragma unroll
        for (int n1 = 0; n1 < 4; n1++) v[n1] = tile[n1 * 32 + lane][wl];
        fft128<+1>(v, lane);
#pragma unroll
        for (int k1 = 0; k1 < 4; k1++) tile[rb * 4 + k1][wl] = v[k1];
    }
    __syncthreads();
#pragma unroll
    for (int j = 0; j < 8; j++) {
        int p = t + j * 256;
        int h = p >> 4, wl = (p & 15) * 2;
        float2 a0 = tile[h][wl], a1 = tile[h][wl + 1];
        *(float4*)(g_XF + pbase + (size_t)h * 128 + w0 + wl) = make_float4(a0.x, a0.y, a1.x, a1.y);
    }
}

// ---------------- K5: IFFT along W + transpose to (B,H,W,C) real out ----------------
__global__ void ifftw_out_kernel(float* __restrict__ out) {
    __shared__ float tile[128][33];
    int bh = blockIdx.y;
    int b = bh >> 7;
    int h = bh & 127;
    int c0 = blockIdx.x * 32;
    int t = threadIdx.x;
    int warp = t >> 5, lane = t & 31;
    int rb = __brev(lane) >> 27;
    const float inv = 1.0f / 16384.0f;
#pragma unroll
    for (int cc4 = 0; cc4 < 4; cc4++) {
        int cl = warp * 4 + cc4;
        size_t rowoff = (size_t)(b * CC + c0 + cl) * HW + (size_t)h * 128;
        float2 v[4];
#pragma unroll
        for (int n1 = 0; n1 < 4; n1++) v[n1] = g_XF[rowoff + n1 * 32 + lane];
        fft128<+1>(v, lane);
#pragma unroll
        for (int k1 = 0; k1 < 4; k1++) tile[rb * 4 + k1][cl] = v[k1].x * inv;
    }
    __syncthreads();
#pragma unroll
    for (int j = 0; j < 4; j++) {
        int i = t + j * 256;                 // 0..1023 float4s
        int w = i >> 3, c4 = (i & 7) * 4;
        float4 v = make_float4(tile[w][c4], tile[w][c4 + 1], tile[w][c4 + 2], tile[w][c4 + 3]);
        *(float4*)(out + (size_t)bh * (WD * CC) + (size_t)w * CC + c0 + c4) = v;
    }
}

extern "C" void kernel_launch(void* const* d_in, const int* in_sizes, int n_in,
                              void* d_out, int out_size) {
    const float* x   = (const float*)d_in[0];
    const float* Ak  = (const float*)d_in[1];
    const float* Bk  = (const float*)d_in[2];
    const float* Wma = (const float*)d_in[3];
    const float* bma = (const float*)d_in[4];
    const float* Wpa = (const float*)d_in[5];
    const float* bpa = (const float*)d_in[6];
    const float* Wmb = (const float*)d_in[7];
    const float* bmb = (const float*)d_in[8];
    const float* Wpb = (const float*)d_in[9];
    const float* bpb = (const float*)d_in[10];
    float* out = (float*)d_out;

    cudaFuncSetAttribute(gemm_mma_kernel, cudaFuncAttributeMaxDynamicSharedMemorySize, GEMM_SMEM);

    pack_kernel<<<1024, 256>>>(Wma, Wpa, Wmb, Wpb, bma, bpa, bmb, bpb);
    kfreq_kernel<<<dim3(128, 256), 128>>>(Ak, Bk);
    fftw_kernel<<<dim3(8, 1024), 256>>>(x);
    gemm_mma_kernel<<<dim3(4, 2048), 256, GEMM_SMEM>>>();
    ffth_pointwise_kernel<<<dim3(4, 2048), 256>>>();
    ifftw_out_kernel<<<dim3(8, 1024), 256>>>(out);
}

// round 17
// speedup vs baseline: 1.6750x; 1.0402x over previous
#include <cuda_runtime.h>
#include <cuda_bf16.h>
#include <cstdint>
#include <math.h>

#define BB   8
#define HD   128
#define WD   128
#define CC   256
#define HW   16384
#define NPLANE 2048
#define TWOPI 6.28318530717958647692f

// ---------------- scratch ----------------
__device__ __align__(16) float2 g_AF[CC * HW];
__device__ __align__(16) float2 g_BF[CC * HW];
__device__ __align__(16) float2 g_XF[NPLANE * HW];
__device__ __align__(16) float2 g_GA[NPLANE * HW];
__device__ __align__(16) float2 g_GB[NPLANE * HW];
__device__ __align__(16) __nv_bfloat16 g_WbHi[1024 * 256];   // [n][k], n = d*4+m
__device__ __align__(16) __nv_bfloat16 g_WbLo[1024 * 256];
__device__ __align__(16) __nv_bfloat16 g_XHi[131072 * 256];  // [pix][c] bf16 hi
__device__ __align__(16) __nv_bfloat16 g_XLo[131072 * 256];  // [pix][c] bf16 lo
__device__ float  g_bpk[1024];

// ---------------- complex helpers ----------------
__device__ __forceinline__ float2 cmul(float2 a, float2 b) {
    return make_float2(a.x * b.x - a.y * b.y, a.x * b.y + a.y * b.x);
}
__device__ __forceinline__ float2 cadd(float2 a, float2 b) { return make_float2(a.x + b.x, a.y + b.y); }
__device__ __forceinline__ float2 csub(float2 a, float2 b) { return make_float2(a.x - b.x, a.y - b.y); }
__device__ __forceinline__ float2 cconj(float2 a) { return make_float2(a.x, -a.y); }

__device__ __forceinline__ float2 shfl_xor_c(float2 v, int m) {
    float2 r;
    r.x = __shfl_xor_sync(0xffffffffu, v.x, m);
    r.y = __shfl_xor_sync(0xffffffffu, v.y, m);
    return r;
}

__device__ __forceinline__ uint32_t smem_u32(const void* p) {
    uint32_t a;
    asm("{ .reg .u64 t; cvta.to.shared.u64 t, %1; cvt.u32.u64 %0, t; }" : "=r"(a) : "l"(p));
    return a;
}
__device__ __forceinline__ void ldsm4(uint32_t* r, uint32_t addr) {
    asm volatile("ldmatrix.sync.aligned.m8n8.x4.shared.b16 {%0,%1,%2,%3}, [%4];"
                 : "=r"(r[0]), "=r"(r[1]), "=r"(r[2]), "=r"(r[3]) : "r"(addr));
}
__device__ __forceinline__ void mma16816(float* c, const uint32_t* a, const uint32_t* b) {
    asm volatile("mma.sync.aligned.m16n8k16.row.col.f32.bf16.bf16.f32 "
                 "{%0,%1,%2,%3}, {%4,%5,%6,%7}, {%8,%9}, {%0,%1,%2,%3};"
                 : "+f"(c[0]), "+f"(c[1]), "+f"(c[2]), "+f"(c[3])
                 : "r"(a[0]), "r"(a[1]), "r"(a[2]), "r"(a[3]), "r"(b[0]), "r"(b[1]));
}
__device__ __forceinline__ void cp16(uint32_t dst, const void* src) {
    asm volatile("cp.async.cg.shared.global [%0], [%1], 16;" :: "r"(dst), "l"(src) : "memory");
}
#define CP_COMMIT() asm volatile("cp.async.commit_group;" ::: "memory")
#define CP_WAIT0()  asm volatile("cp.async.wait_group 0;" ::: "memory")

// 128-pt FFT: 4 regs x 32 lanes. Natural in; out reg k1 @ lane t = index 4*brev5(t)+k1.
template <int SGN>
__device__ __forceinline__ void fft128(float2 v[4], int lane) {
    float2 t0 = cadd(v[0], v[2]);
    float2 t1 = csub(v[0], v[2]);
    float2 t2 = cadd(v[1], v[3]);
    float2 t3 = csub(v[1], v[3]);
    float2 jt3 = make_float2(-t3.y, t3.x);
    float2 y0 = cadd(t0, t2);
    float2 y2 = csub(t0, t2);
    float2 y1, y3;
    if (SGN < 0) { y1 = csub(t1, jt3); y3 = cadd(t1, jt3); }
    else         { y1 = cadd(t1, jt3); y3 = csub(t1, jt3); }
    float ss, cc;
    __sincosf((float)SGN * TWOPI * (float)lane * (1.0f / 128.0f), &ss, &cc);
    float2 w1 = make_float2(cc, ss);
    float2 w2 = cmul(w1, w1);
    float2 w3 = cmul(w2, w1);
    v[0] = y0;
    v[1] = cmul(y1, w1);
    v[2] = cmul(y2, w2);
    v[3] = cmul(y3, w3);
#pragma unroll
    for (int h = 16; h >= 1; h >>= 1) {
        int j = lane & (h - 1);
        float ang = (float)SGN * TWOPI * (float)j / (float)(2 * h);
        float ws, wc;
        __sincosf(ang, &ws, &wc);
        float2 w = make_float2(wc, ws);
        bool hi = (lane & h) != 0;
#pragma unroll
        for (int k = 0; k < 4; k++) {
            float2 o = shfl_xor_c(v[k], h);
            if (hi) v[k] = cmul(csub(o, v[k]), w);
            else    v[k] = cadd(v[k], o);
        }
    }
}

// ---------------- K0: pack weights (bf16 hi/lo, [n][k]) + biases ----------------
__global__ void pack_kernel(const float* __restrict__ Wma, const float* __restrict__ Wpa,
                            const float* __restrict__ Wmb, const float* __restrict__ Wpb,
                            const float* __restrict__ bma, const float* __restrict__ bpa,
                            const float* __restrict__ bmb, const float* __restrict__ bpb) {
    int i = blockIdx.x * 256 + threadIdx.x;
    if (i < 1024 * 256) {
        int n = i >> 8, k = i & 255;
        int d = n >> 2, m = n & 3;
        const float* Wm = (m == 0) ? Wma : (m == 1) ? Wpa : (m == 2) ? Wmb : Wpb;
        float w = Wm[k * 256 + d];
        __nv_bfloat16 hi = __float2bfloat16(w);
        __nv_bfloat16 lo = __float2bfloat16(w - __bfloat162float(hi));
        g_WbHi[(size_t)n * 256 + k] = hi;
        g_WbLo[(size_t)n * 256 + k] = lo;
    }
    if (i < 1024) {
        int d = i >> 2, m = i & 3;
        const float* bv = (m == 0) ? bma : (m == 1) ? bpa : (m == 2) ? bmb : bpb;
        g_bpk[i] = bv[d];
    }
}

// ---------------- K1: freq-domain conv kernels (49-tap DFT) ----------------
__global__ void kfreq_kernel(const float* __restrict__ Ak, const float* __restrict__ Bk) {
    int w = threadIdx.x;
    int h = blockIdx.x;
    int c = blockIdx.y;
    __shared__ float ka[49], kb[49];
    if (threadIdx.x < 49) {
        ka[threadIdx.x] = Ak[c * 49 + threadIdx.x];
        kb[threadIdx.x] = Bk[c * 49 + threadIdx.x];
    }
    __syncthreads();
    float2 eh[7], ew[7];
    {
        float s, ct;
        sincosf(-TWOPI * (float)h * (1.0f / 128.0f), &s, &ct);
        float2 b1 = make_float2(ct, s);
        eh[3] = make_float2(1.f, 0.f);
        eh[4] = b1; eh[5] = cmul(b1, b1); eh[6] = cmul(eh[5], b1);
        eh[2] = cconj(eh[4]); eh[1] = cconj(eh[5]); eh[0] = cconj(eh[6]);
        sincosf(-TWOPI * (float)w * (1.0f / 128.0f), &s, &ct);
        float2 b2 = make_float2(ct, s);
        ew[3] = make_float2(1.f, 0.f);
        ew[4] = b2; ew[5] = cmul(b2, b2); ew[6] = cmul(ew[5], b2);
        ew[2] = cconj(ew[4]); ew[1] = cconj(ew[5]); ew[0] = cconj(ew[6]);
    }
    float2 accA = make_float2(0.f, 0.f), accB = make_float2(0.f, 0.f);
#pragma unroll
    for (int i = 0; i < 7; i++) {
        float2 rowA = make_float2(0.f, 0.f), rowB = make_float2(0.f, 0.f);
#pragma unroll
        for (int j = 0; j < 7; j++) {
            float va = ka[i * 7 + j], vb = kb[i * 7 + j];
            rowA.x += va * ew[j].x; rowA.y += va * ew[j].y;
            rowB.x += vb * ew[j].x; rowB.y += vb * ew[j].y;
        }
        accA = cadd(accA, cmul(eh[i], rowA));
        accB = cadd(accB, cmul(eh[i], rowB));
    }
    size_t idx = (size_t)c * HW + h * 128 + w;
    g_AF[idx] = accA;
    g_BF[idx] = accB;
}

// ---------------- K3: FFT along W + transpose to planar + bf16 split of x ----------------
__global__ void fftw_kernel(const float* __restrict__ x) {
    __shared__ float tile[128][33];
    int bh = blockIdx.y;
    int b = bh >> 7;
    int c0 = blockIdx.x * 32;
    int t = threadIdx.x;
#pragma unroll
    for (int j = 0; j < 4; j++) {
        int i = t + j * 256;                 // 0..1023 float4s
        int w = i >> 3, c4 = (i & 7) * 4;
        float4 v = *(const float4*)(x + (size_t)bh * (WD * CC) + (size_t)w * CC + c0 + c4);
        tile[w][c4 + 0] = v.x; tile[w][c4 + 1] = v.y;
        tile[w][c4 + 2] = v.z; tile[w][c4 + 3] = v.w;
        __nv_bfloat16 h0 = __float2bfloat16(v.x), h1 = __float2bfloat16(v.y);
        __nv_bfloat16 h2 = __float2bfloat16(v.z), h3 = __float2bfloat16(v.w);
        __nv_bfloat16 l0 = __float2bfloat16(v.x - __bfloat162float(h0));
        __nv_bfloat16 l1 = __float2bfloat16(v.y - __bfloat162float(h1));
        __nv_bfloat16 l2 = __float2bfloat16(v.z - __bfloat162float(h2));
        __nv_bfloat16 l3 = __float2bfloat16(v.w - __bfloat162float(h3));
        size_t pi = ((size_t)bh * 128 + w) * 256 + c0 + c4;
        __nv_bfloat162 ph01, ph23, pl01, pl23;
        ph01.x = h0; ph01.y = h1; ph23.x = h2; ph23.y = h3;
        pl01.x = l0; pl01.y = l1; pl23.x = l2; pl23.y = l3;
        uint2 uh, ul;
        uh.x = *reinterpret_cast<uint32_t*>(&ph01); uh.y = *reinterpret_cast<uint32_t*>(&ph23);
        ul.x = *reinterpret_cast<uint32_t*>(&pl01); ul.y = *reinterpret_cast<uint32_t*>(&pl23);
        *(uint2*)(g_XHi + pi) = uh;
        *(uint2*)(g_XLo + pi) = ul;
    }
    __syncthreads();
    int warp = t >> 5, lane = t & 31;
    int rb = __brev(lane) >> 27;
    int h = bh & 127;
#pragma unroll
    for (int cc4 = 0; cc4 < 4; cc4++) {
        int cl = warp * 4 + cc4;
        float2 v[4];
#pragma unroll
        for (int n1 = 0; n1 < 4; n1++) v[n1] = make_float2(tile[n1 * 32 + lane][cl], 0.f);
        fft128<-1>(v, lane);
        size_t rowoff = (size_t)(b * CC + c0 + cl) * HW + (size_t)h * 128 + rb * 4;
        *(float4*)(g_XF + rowoff)     = make_float4(v[0].x, v[0].y, v[1].x, v[1].y);
        *(float4*)(g_XF + rowoff + 2) = make_float4(v[2].x, v[2].y, v[3].x, v[3].y);
    }
}

// ---------------- K2: HMMA GEMM, 64x128 tile, serial K=64 chunks, 3 CTAs/SM ----------------
#define STRD 144                              // 72 elems * 2B row stride
#define OFF_AH 0
#define OFF_AL 9216
#define OFF_BH 18432
#define OFF_BL 36864
#define GEMM_SMEM 55296                       // 54 KB; Z tile (128*66*4=33792) aliases
#define Z_STRIDE 66

__global__ __launch_bounds__(256, 3) void gemm_mma_kernel() {
    extern __shared__ char smem[];
    uint32_t sb = smem_u32(smem);
    int tid = threadIdx.x;
    int lane = tid & 31, warp = tid >> 5;
    int wm = warp >> 2, wn = warp & 3;        // 2 m-groups x 4 n-groups, warp tile 32x32
    int n0 = blockIdx.x * 128;
    size_t pixbase = (size_t)blockIdx.y * 64;

    float acc[2][4][4];
#pragma unroll
    for (int i = 0; i < 2; i++)
#pragma unroll
        for (int j = 0; j < 4; j++)
#pragma unroll
            for (int k = 0; k < 4; k++) acc[i][j][k] = 0.f;

    int sub = lane >> 3, l7 = lane & 7;
    int a_r = ((sub & 1) << 3) + l7;
    int a_k = (sub >> 1) << 3;
    int b_r = ((sub >> 1) << 3) + l7;
    int b_k = (sub & 1) << 3;

#pragma unroll
    for (int kc = 0; kc < 4; kc++) {
        __syncthreads();                      // buffer reuse guard
        // A: 64 rows x 64 k (hi+lo): 512 segs each -> 2/thread
        {
            int u = tid << 1;
            int row = u >> 3, seg = u & 7;
            size_t gofs = (pixbase + row) * 256 + kc * 64 + seg * 8;
            uint32_t d = (uint32_t)(row * STRD + seg * 16);
            cp16(sb + OFF_AH + d,      g_XHi + gofs);
            cp16(sb + OFF_AH + d + 16, g_XHi + gofs + 8);
            cp16(sb + OFF_AL + d,      g_XLo + gofs);
            cp16(sb + OFF_AL + d + 16, g_XLo + gofs + 8);
        }
        // B: 128 rows x 64 k (hi+lo): 1024 segs each -> 4/thread
#pragma unroll
        for (int it = 0; it < 4; it++) {
            int u = tid + it * 256;
            int row = u >> 3, seg = u & 7;
            size_t gofs = (size_t)(n0 + row) * 256 + kc * 64 + seg * 8;
            uint32_t d = (uint32_t)(row * STRD + seg * 16);
            cp16(sb + OFF_BH + d, g_WbHi + gofs);
            cp16(sb + OFF_BL + d, g_WbLo + gofs);
        }
        CP_COMMIT();
        CP_WAIT0();
        __syncthreads();

#pragma unroll
        for (int ks = 0; ks < 4; ks++) {
            uint32_t ah[2][4], al[2][4];
#pragma unroll
            for (int mt = 0; mt < 2; mt++) {
                uint32_t aoff = (uint32_t)((wm * 32 + mt * 16 + a_r) * STRD + (ks * 16 + a_k) * 2);
                ldsm4(ah[mt], sb + OFF_AH + aoff);
                ldsm4(al[mt], sb + OFF_AL + aoff);
            }
#pragma unroll
            for (int ntp = 0; ntp < 2; ntp++) {
                uint32_t bh[4], bl[4];
                uint32_t boff = (uint32_t)((wn * 32 + ntp * 16 + b_r) * STRD + (ks * 16 + b_k) * 2);
                ldsm4(bh, sb + OFF_BH + boff);
                ldsm4(bl, sb + OFF_BL + boff);
                mma16816(acc[0][2 * ntp],     ah[0], bh);
                mma16816(acc[0][2 * ntp + 1], ah[0], bh + 2);
                mma16816(acc[1][2 * ntp],     ah[1], bh);
                mma16816(acc[1][2 * ntp + 1], ah[1], bh + 2);
                mma16816(acc[0][2 * ntp],     ah[0], bl);
                mma16816(acc[0][2 * ntp + 1], ah[0], bl + 2);
                mma16816(acc[1][2 * ntp],     ah[1], bl);
                mma16816(acc[1][2 * ntp + 1], ah[1], bl + 2);
                mma16816(acc[0][2 * ntp],     al[0], bh);
                mma16816(acc[0][2 * ntp + 1], al[0], bh + 2);
                mma16816(acc[1][2 * ntp],     al[1], bh);
                mma16816(acc[1][2 * ntp + 1], al[1], bh + 2);
            }
        }
    }

    // ---- epilogue: Z (transposed, 128 cols x 64 rows) in SMEM, then gates ----
    __syncthreads();
    float* zs = (float*)smem;
    {
        int r0 = wm * 32 + (lane >> 2);
        int c0 = wn * 32 + 2 * (lane & 3);
#pragma unroll
        for (int mt = 0; mt < 2; mt++)
#pragma unroll
            for (int nt = 0; nt < 4; nt++) {
                int rr = r0 + mt * 16;
                int cc = c0 + nt * 8;
                zs[cc * Z_STRIDE + rr]           = acc[mt][nt][0];
                zs[(cc + 1) * Z_STRIDE + rr]     = acc[mt][nt][1];
                zs[cc * Z_STRIDE + rr + 8]       = acc[mt][nt][2];
                zs[(cc + 1) * Z_STRIDE + rr + 8] = acc[mt][nt][3];
            }
    }
    __syncthreads();
    {
        int pr = tid & 63;
        int dgrp = tid >> 6;                  // 0..3
        int pix = (int)pixbase + pr;
        int b = pix >> 14;
        int hw = pix & 16383;
#pragma unroll 1
        for (int it = 0; it < 8; it++) {
            int dl = dgrp + it * 4;           // 0..31
            int e0 = dl * 4;
            float zma = zs[e0 * Z_STRIDE + pr]       + g_bpk[n0 + e0];
            float zpa = zs[(e0 + 1) * Z_STRIDE + pr] + g_bpk[n0 + e0 + 1];
            float zmb = zs[(e0 + 2) * Z_STRIDE + pr] + g_bpk[n0 + e0 + 2];
            float zpb = zs[(e0 + 3) * Z_STRIDE + pr] + g_bpk[n0 + e0 + 3];
            float ma  = 1.0f / (1.0f + __expf(-zma));
            float mbg = 1.0f / (1.0f + __expf(-zmb));
            float sa, ca, sbp, cb;
            __sincosf(zpa, &sa, &ca);
            __sincosf(zpb, &sbp, &cb);
            int d = (n0 >> 2) + dl;
            size_t po = (size_t)(b * 256 + d) * HW + hw;
            g_GA[po] = make_float2(ma * ca, ma * sa);
            g_GB[po] = make_float2(mbg * cb, mbg * sbp);
        }
    }
}

// ---------------- K4: FFT-H + pointwise recurrence + IFFT-H ----------------
__global__ void ffth_pointwise_kernel() {
    __shared__ float2 tile[128][33];
    int plane = blockIdx.y;
    int c = plane & 255;
    int w0 = blockIdx.x * 32;
    int t = threadIdx.x;
    size_t pbase = (size_t)plane * HW;
    size_t cbase = (size_t)c * HW;
#pragma unroll
    for (int j = 0; j < 8; j++) {
        int p = t + j * 256;                  // 0..2047 float2-pairs
        int h = p >> 4, wl = (p & 15) * 2;
        float4 v = *(const float4*)(g_XF + pbase + (size_t)h * 128 + w0 + wl);
        tile[h][wl]     = make_float2(v.x, v.y);
        tile[h][wl + 1] = make_float2(v.z, v.w);
    }
    __syncthreads();
    int warp = t >> 5, lane = t & 31;
    int rb = __brev(lane) >> 27;
#pragma unroll
    for (int cc4 = 0; cc4 < 4; cc4++) {
        int wl = warp * 4 + cc4;
        float2 v[4];
#pragma unroll
        for (int n1 = 0; n1 < 4; n1++) v[n1] = tile[n1 * 32 + lane][wl];
        fft128<-1>(v, lane);
#pragma unroll
        for (int k1 = 0; k1 < 4; k1++) tile[rb * 4 + k1][wl] = v[k1];
    }
    __syncthreads();
#pragma unroll
    for (int j = 0; j < 8; j++) {
        int p = t + j * 256;
        int h = p >> 4, wl = (p & 15) * 2;
        size_t off = (size_t)h * 128 + w0 + wl;
        float4 gav = *(const float4*)(g_GA + pbase + off);
        float4 gbv = *(const float4*)(g_GB + pbase + off);
        float4 afv = *(const float4*)(g_AF + cbase + off);
        float4 bfv = *(const float4*)(g_BF + cbase + off);
#pragma unroll
        for (int e = 0; e < 2; e++) {
            float2 xf = tile[h][wl + e];
            float2 ga = e ? make_float2(gav.z, gav.w) : make_float2(gav.x, gav.y);
            float2 gb = e ? make_float2(gbv.z, gbv.w) : make_float2(gbv.x, gbv.y);
            float2 af = e ? make_float2(afv.z, afv.w) : make_float2(afv.x, afv.y);
            float2 bf = e ? make_float2(bfv.z, bfv.w) : make_float2(bfv.x, bfv.y);
            float2 a  = cmul(ga, af);
            float2 bb = cmul(cmul(gb, bf), xf);
            float2 a2 = cmul(a, a);
            float2 a4 = cmul(a2, a2);
            float2 p1 = make_float2(1.f + a.x,  a.y);
            float2 p2 = make_float2(1.f + a2.x, a2.y);
            float2 p4 = make_float2(1.f + a4.x, a4.y);
            tile[h][wl + e] = cmul(bb, cmul(cmul(p1, p2), p4));
        }
    }
    __syncthreads();
#pragma unroll
    for (int cc4 = 0; cc4 < 4; cc4++) {
        int wl = warp * 4 + cc4;
        float2 v[4];
#pragma unroll
        for (int n1 = 0; n1 < 4; n1++) v[n1] = tile[n1 * 32 + lane][wl];
        fft128<+1>(v, lane);
#pragma unroll
        for (int k1 = 0; k1 < 4; k1++) tile[rb * 4 + k1][wl] = v[k1];
    }
    __syncthreads();
#pragma unroll
    for (int j = 0; j < 8; j++) {
        int p = t + j * 256;
        int h = p >> 4, wl = (p & 15) * 2;
        float2 a0 = tile[h][wl], a1 = tile[h][wl + 1];
        *(float4*)(g_XF + pbase + (size_t)h * 128 + w0 + wl) = make_float4(a0.x, a0.y, a1.x, a1.y);
    }
}

// ---------------- K5: IFFT along W + transpose to (B,H,W,C) real out ----------------
__global__ void ifftw_out_kernel(float* __restrict__ out) {
    __shared__ float tile[128][33];
    int bh = blockIdx.y;
    int b = bh >> 7;
    int h = bh & 127;
    int c0 = blockIdx.x * 32;
    int t = threadIdx.x;
    int warp = t >> 5, lane = t & 31;
    int rb = __brev(lane) >> 27;
    const float inv = 1.0f / 16384.0f;
#pragma unroll
    for (int cc4 = 0; cc4 < 4; cc4++) {
        int cl = warp * 4 + cc4;
        size_t rowoff = (size_t)(b * CC + c0 + cl) * HW + (size_t)h * 128;
        float2 v[4];
#pragma unroll
        for (int n1 = 0; n1 < 4; n1++) v[n1] = g_XF[rowoff + n1 * 32 + lane];
        fft128<+1>(v, lane);
#pragma unroll
        for (int k1 = 0; k1 < 4; k1++) tile[rb * 4 + k1][cl] = v[k1].x * inv;
    }
    __syncthreads();
#pragma unroll
    for (int j = 0; j < 4; j++) {
        int i = t + j * 256;                 // 0..1023 float4s
        int w = i >> 3, c4 = (i & 7) * 4;
        float4 v = make_float4(tile[w][c4], tile[w][c4 + 1], tile[w][c4 + 2], tile[w][c4 + 3]);
        *(float4*)(out + (size_t)bh * (WD * CC) + (size_t)w * CC + c0 + c4) = v;
    }
}

extern "C" void kernel_launch(void* const* d_in, const int* in_sizes, int n_in,
                              void* d_out, int out_size) {
    const float* x   = (const float*)d_in[0];
    const float* Ak  = (const float*)d_in[1];
    const float* Bk  = (const float*)d_in[2];
    const float* Wma = (const float*)d_in[3];
    const float* bma = (const float*)d_in[4];
    const float* Wpa = (const float*)d_in[5];
    const float* bpa = (const float*)d_in[6];
    const float* Wmb = (const float*)d_in[7];
    const float* bmb = (const float*)d_in[8];
    const float* Wpb = (const float*)d_in[9];
    const float* bpb = (const float*)d_in[10];
    float* out = (float*)d_out;

    cudaFuncSetAttribute(gemm_mma_kernel, cudaFuncAttributeMaxDynamicSharedMemorySize, GEMM_SMEM);

    pack_kernel<<<1024, 256>>>(Wma, Wpa, Wmb, Wpb, bma, bpa, bmb, bpb);
    kfreq_kernel<<<dim3(128, 256), 128>>>(Ak, Bk);
    fftw_kernel<<<dim3(8, 1024), 256>>>(x);
    gemm_mma_kernel<<<dim3(8, 2048), 256, GEMM_SMEM>>>();
    ffth_pointwise_kernel<<<dim3(4, 2048), 256>>>();
    ifftw_out_kernel<<<dim3(8, 1024), 256>>>(out);
}